// round 1
// baseline (speedup 1.0000x reference)
#include <cuda_runtime.h>

#define S_LEN   2048
#define NB      2
#define DMODEL  1024
#define NHEAD   16
#define DKH     64
#define MROWS   (S_LEN * NB)   // 4096
#define PAD     68             // smem row stride (floats), keeps 16B alignment, odd*4 banks

// Scratch: Q/K/V in [b][h][s][dk] layout, attention output in [s][b][d_model]
__device__ float g_Q [NB * NHEAD * S_LEN * DKH];
__device__ float g_K [NB * NHEAD * S_LEN * DKH];
__device__ float g_V [NB * NHEAD * S_LEN * DKH];
__device__ float g_AO[MROWS * DMODEL];

// ---------------------------------------------------------------------------
// SGEMM: out = X[M,K] @ W[N,K]^T + bias, M=4096, N=K=1024.
// mode 0: out[m*N+n]  (row-major, used for output projection -> d_out)
// mode 1: scatter to [b][h][s][dk] layout (used for Q/K/V projections)
// BM=BN=128, BK=8, 256 threads, 8x8 per-thread microtile.
// ---------------------------------------------------------------------------
__global__ void __launch_bounds__(256, 2)
gemm_kernel(const float* __restrict__ X, const float* __restrict__ W,
            const float* __restrict__ bias, float* __restrict__ out, int mode)
{
    __shared__ float As[8][128];
    __shared__ float Bs[8][128];

    const int tid  = threadIdx.x;
    const int m0   = blockIdx.y * 128;
    const int n0   = blockIdx.x * 128;
    const int tx   = tid & 15;
    const int ty   = tid >> 4;
    const int lrow = tid >> 1;          // 0..127
    const int lc   = (tid & 1) * 4;     // 0 or 4

    const float* Xp = X + (size_t)(m0 + lrow) * DMODEL + lc;
    const float* Wp = W + (size_t)(n0 + lrow) * DMODEL + lc;

    float acc[8][8];
#pragma unroll
    for (int i = 0; i < 8; i++)
#pragma unroll
        for (int j = 0; j < 8; j++) acc[i][j] = 0.0f;

    for (int k0 = 0; k0 < DMODEL; k0 += 8) {
        float4 av = *(const float4*)(Xp + k0);
        float4 bv = *(const float4*)(Wp + k0);
        __syncthreads();
        As[lc + 0][lrow] = av.x; As[lc + 1][lrow] = av.y;
        As[lc + 2][lrow] = av.z; As[lc + 3][lrow] = av.w;
        Bs[lc + 0][lrow] = bv.x; Bs[lc + 1][lrow] = bv.y;
        Bs[lc + 2][lrow] = bv.z; Bs[lc + 3][lrow] = bv.w;
        __syncthreads();
#pragma unroll
        for (int kk = 0; kk < 8; kk++) {
            float a[8], b[8];
            *(float4*)&a[0] = *(const float4*)&As[kk][ty * 8];
            *(float4*)&a[4] = *(const float4*)&As[kk][ty * 8 + 4];
            *(float4*)&b[0] = *(const float4*)&Bs[kk][tx * 8];
            *(float4*)&b[4] = *(const float4*)&Bs[kk][tx * 8 + 4];
#pragma unroll
            for (int i = 0; i < 8; i++)
#pragma unroll
                for (int j = 0; j < 8; j++)
                    acc[i][j] = fmaf(a[i], b[j], acc[i][j]);
        }
    }

#pragma unroll
    for (int i = 0; i < 8; i++) {
        const int m = m0 + ty * 8 + i;
#pragma unroll
        for (int j = 0; j < 8; j++) {
            const int n = n0 + tx * 8 + j;
            const float v = acc[i][j] + bias[n];
            if (mode == 0) {
                out[(size_t)m * DMODEL + n] = v;
            } else {
                const int b = m & 1;       // batch (B=2), row m = s*B + b
                const int s = m >> 1;
                const int h = n >> 6;      // head
                const int d = n & 63;
                out[(((size_t)(b * NHEAD + h)) * S_LEN + s) * DKH + d] = v;
            }
        }
    }
}

// ---------------------------------------------------------------------------
// Flash attention: per (b,h), 64-query tiles, 64-key tiles, online softmax.
// Thread grid 16x16, each thread owns a 4x4 tile of scores / output.
// Smem tiles stored transposed so inner loops are broadcast / conflict-free
// float4 loads. Scale 1/sqrt(64)=0.125 folded into Q.
// Output written to g_AO in [s][b][d_model] layout.
// ---------------------------------------------------------------------------
__global__ void __launch_bounds__(256)
flash_kernel(float* __restrict__ Og)
{
    extern __shared__ float sm[];
    float* Qs = sm;                 // [d=64][PAD]  Qs[d][q]
    float* Ks = Qs + 64 * PAD;      // [d=64][PAD]  Ks[d][k]
    float* Vs = Ks + 64 * PAD;      // [k=64][PAD]  Vs[k][d]
    float* Ps = Vs + 64 * PAD;      // [k=64][PAD]  Ps[k][q]

    const int tid = threadIdx.x;
    const int tx  = tid & 15;
    const int ty  = tid >> 4;
    const int bh  = blockIdx.y;             // b*NHEAD + h
    const int q0  = blockIdx.x * 64;

    const float* Qb = g_Q + ((size_t)bh * S_LEN + q0) * DKH;
    const float* Kb = g_K + (size_t)bh * S_LEN * DKH;
    const float* Vb = g_V + (size_t)bh * S_LEN * DKH;

    // Load Q tile transposed, fold softmax scale
    for (int i = tid; i < 64 * 64; i += 256) {
        const int r = i >> 6, c = i & 63;
        Qs[c * PAD + r] = Qb[i] * 0.125f;
    }

    float mrun[4], lrun[4], o[4][4];
#pragma unroll
    for (int i = 0; i < 4; i++) {
        mrun[i] = -1e30f;
        lrun[i] = 0.0f;
#pragma unroll
        for (int j = 0; j < 4; j++) o[i][j] = 0.0f;
    }

    for (int kt = 0; kt < S_LEN; kt += 64) {
        __syncthreads();   // protect Ks/Vs/Ps from previous iteration
        // Load K tile transposed, V tile row-major
        for (int i = tid; i < 64 * 64; i += 256) {
            const int r = i >> 6, c = i & 63;
            Ks[c * PAD + r] = Kb[(size_t)kt * DKH + i];
        }
        for (int i = tid; i < 64 * 16; i += 256) {
            const int r = i >> 4, c4 = i & 15;
            *(float4*)&Vs[r * PAD + c4 * 4] =
                *(const float4*)&Vb[(size_t)(kt + r) * DKH + c4 * 4];
        }
        __syncthreads();

        // Scores: s[i][j] = sum_d Q[q0+ty*4+i][d] * K[kt+tx*4+j][d] (prescaled)
        float s[4][4];
#pragma unroll
        for (int i = 0; i < 4; i++)
#pragma unroll
            for (int j = 0; j < 4; j++) s[i][j] = 0.0f;

#pragma unroll 4
        for (int d = 0; d < 64; d++) {
            float a[4], b[4];
            *(float4*)a = *(const float4*)&Qs[d * PAD + ty * 4];
            *(float4*)b = *(const float4*)&Ks[d * PAD + tx * 4];
#pragma unroll
            for (int i = 0; i < 4; i++)
#pragma unroll
                for (int j = 0; j < 4; j++)
                    s[i][j] = fmaf(a[i], b[j], s[i][j]);
        }

        // Online softmax per query row (row owned by 16-lane group, same ty)
#pragma unroll
        for (int i = 0; i < 4; i++) {
            float mx = fmaxf(fmaxf(s[i][0], s[i][1]), fmaxf(s[i][2], s[i][3]));
#pragma unroll
            for (int off = 8; off > 0; off >>= 1)
                mx = fmaxf(mx, __shfl_xor_sync(0xffffffffu, mx, off, 16));
            const float mnew  = fmaxf(mrun[i], mx);
            const float alpha = __expf(mrun[i] - mnew);
            mrun[i] = mnew;
            float rs = 0.0f;
#pragma unroll
            for (int j = 0; j < 4; j++) {
                s[i][j] = __expf(s[i][j] - mnew);
                rs += s[i][j];
            }
#pragma unroll
            for (int off = 8; off > 0; off >>= 1)
                rs += __shfl_xor_sync(0xffffffffu, rs, off, 16);
            lrun[i] = lrun[i] * alpha + rs;
#pragma unroll
            for (int j = 0; j < 4; j++) o[i][j] *= alpha;
        }

        // Stash P transposed: Ps[k][q]
#pragma unroll
        for (int j = 0; j < 4; j++)
#pragma unroll
            for (int i = 0; i < 4; i++)
                Ps[(tx * 4 + j) * PAD + ty * 4 + i] = s[i][j];
        __syncthreads();

        // O += P @ V : o[i][j] += sum_k P[q][k] * V[k][d]
#pragma unroll 4
        for (int k = 0; k < 64; k++) {
            float a[4], b[4];
            *(float4*)a = *(const float4*)&Ps[k * PAD + ty * 4];
            *(float4*)b = *(const float4*)&Vs[k * PAD + tx * 4];
#pragma unroll
            for (int i = 0; i < 4; i++)
#pragma unroll
                for (int j = 0; j < 4; j++)
                    o[i][j] = fmaf(a[i], b[j], o[i][j]);
        }
    }

    // Write O / l to g_AO[s][b][h*64 + d]
    const int bb = bh >> 4;
    const int hh = bh & 15;
#pragma unroll
    for (int i = 0; i < 4; i++) {
        const float inv = 1.0f / lrun[i];
        const int qg = q0 + ty * 4 + i;
        float4 v = make_float4(o[i][0] * inv, o[i][1] * inv,
                               o[i][2] * inv, o[i][3] * inv);
        *(float4*)&Og[((size_t)qg * NB + bb) * DMODEL + hh * DKH + tx * 4] = v;
    }
}

// ---------------------------------------------------------------------------
extern "C" void kernel_launch(void* const* d_in, const int* in_sizes, int n_in,
                              void* d_out, int out_size)
{
    const float* q  = (const float*)d_in[0];
    const float* k  = (const float*)d_in[1];
    const float* v  = (const float*)d_in[2];
    const float* Wq = (const float*)d_in[3];
    const float* bq = (const float*)d_in[4];
    const float* Wk = (const float*)d_in[5];
    const float* bk = (const float*)d_in[6];
    const float* Wv = (const float*)d_in[7];
    const float* bv = (const float*)d_in[8];
    const float* Wo = (const float*)d_in[9];
    const float* bo = (const float*)d_in[10];
    float* out = (float*)d_out;

    float *gq, *gk, *gv, *gao;
    cudaGetSymbolAddress((void**)&gq,  g_Q);
    cudaGetSymbolAddress((void**)&gk,  g_K);
    cudaGetSymbolAddress((void**)&gv,  g_V);
    cudaGetSymbolAddress((void**)&gao, g_AO);

    const dim3 ggrid(DMODEL / 128, MROWS / 128);   // (8, 32)

    gemm_kernel<<<ggrid, 256>>>(q, Wq, bq, gq, 1);
    gemm_kernel<<<ggrid, 256>>>(k, Wk, bk, gk, 1);
    gemm_kernel<<<ggrid, 256>>>(v, Wv, bv, gv, 1);

    const size_t smem = 4 * 64 * PAD * sizeof(float);   // 69,632 B
    cudaFuncSetAttribute(flash_kernel,
                         cudaFuncAttributeMaxDynamicSharedMemorySize, (int)smem);
    flash_kernel<<<dim3(S_LEN / 64, NB * NHEAD), 256, smem>>>(gao);

    gemm_kernel<<<ggrid, 256>>>(gao, Wo, bo, out, 0);
}

// round 3
// speedup vs baseline: 1.5238x; 1.5238x over previous
#include <cuda_runtime.h>
#include <cuda_bf16.h>
#include <cstdint>

#define S_LEN   2048
#define NB      2
#define DMODEL  1024
#define NHEAD   16
#define DKH     64
#define MROWS   (S_LEN * NB)   // 4096
#define PAD     68

#if defined(__CUDA_ARCH_FEAT_SM103_ALL) || defined(__CUDA_ARCH_FEAT_SM100_ALL)
#define HAS_TCGEN05 1
#else
#define HAS_TCGEN05 0
#endif

// Scratch: Q/K/V and attention output, all row-major [m][n] = [4096][1024]
__device__ float g_Q [MROWS * DMODEL];
__device__ float g_K [MROWS * DMODEL];
__device__ float g_V [MROWS * DMODEL];
__device__ float g_AO[MROWS * DMODEL];

// ---------------------------------------------------------------------------
// PTX helpers (macros expand only inside the guarded fast path)
// ---------------------------------------------------------------------------
__device__ __forceinline__ uint32_t smem_u32(const void* p) {
    uint32_t a;
    asm("{ .reg .u64 t; cvta.to.shared.u64 t, %1; cvt.u32.u64 %0, t; }"
        : "=r"(a) : "l"(p));
    return a;
}
__device__ __forceinline__ uint32_t elect_one() {
    uint32_t p;
    asm volatile("{ .reg .pred p; elect.sync _|p, 0xFFFFFFFF; selp.b32 %0,1,0,p; }"
                 : "=r"(p));
    return p;
}

#define MBAR_INIT(addr, cnt) \
    asm volatile("mbarrier.init.shared.b64 [%0], %1;" :: "r"(addr), "r"(cnt) : "memory")

#define MBAR_WAIT(addr, parity) do {                                          \
    uint32_t _m = (addr); uint32_t _p = (parity); uint32_t _d;                \
    asm volatile("{ .reg .pred p; mbarrier.try_wait.parity.acquire.cta.shared::cta.b64 p, [%1], %2;" \
                 " selp.b32 %0,1,0,p; }" : "=r"(_d) : "r"(_m), "r"(_p) : "memory"); \
    if (!_d) {                                                                \
        asm volatile("{ .reg .pred P1; WL_%=:"                                \
                     " mbarrier.try_wait.parity.acquire.cta.shared::cta.b64 P1, [%0], %1, 0x989680;" \
                     " @P1 bra.uni WD_%=; bra.uni WL_%=; WD_%=: }"            \
                     :: "r"(_m), "r"(_p) : "memory");                         \
    }                                                                         \
} while (0)

#if HAS_TCGEN05
#define TC_ALLOC(smem_addr, ncols) \
    asm volatile("tcgen05.alloc.cta_group::1.sync.aligned.shared::cta.b32 [%0], %1;" \
                 :: "r"(smem_addr), "r"(ncols) : "memory")
#define TC_RELINQ() \
    asm volatile("tcgen05.relinquish_alloc_permit.cta_group::1.sync.aligned;")
#define TC_DEALLOC(tmem, ncols) \
    asm volatile("tcgen05.dealloc.cta_group::1.sync.aligned.b32 %0, %1;" :: "r"(tmem), "r"(ncols))
#define TC_COMMIT(mbar) \
    asm volatile("tcgen05.commit.cta_group::1.mbarrier::arrive::one.shared::cluster.b64 [%0];" \
                 :: "r"(mbar) : "memory")
#define TC_FENCE_AFTER()  asm volatile("tcgen05.fence::after_thread_sync;" ::: "memory")
#define TC_WAIT_LD()      asm volatile("tcgen05.wait::ld.sync.aligned;" ::: "memory")

#define TC_LD_X32(r, tmem_addr) \
    asm volatile( \
        "tcgen05.ld.sync.aligned.32x32b.x32.b32 " \
        "{%0, %1, %2, %3, %4, %5, %6, %7, %8, %9, %10, %11, %12, %13, %14, %15, " \
        " %16, %17, %18, %19, %20, %21, %22, %23, %24, %25, %26, %27, %28, %29, %30, %31}, [%32];" \
        : "=r"((r)[0]),  "=r"((r)[1]),  "=r"((r)[2]),  "=r"((r)[3]), \
          "=r"((r)[4]),  "=r"((r)[5]),  "=r"((r)[6]),  "=r"((r)[7]), \
          "=r"((r)[8]),  "=r"((r)[9]),  "=r"((r)[10]), "=r"((r)[11]), \
          "=r"((r)[12]), "=r"((r)[13]), "=r"((r)[14]), "=r"((r)[15]), \
          "=r"((r)[16]), "=r"((r)[17]), "=r"((r)[18]), "=r"((r)[19]), \
          "=r"((r)[20]), "=r"((r)[21]), "=r"((r)[22]), "=r"((r)[23]), \
          "=r"((r)[24]), "=r"((r)[25]), "=r"((r)[26]), "=r"((r)[27]), \
          "=r"((r)[28]), "=r"((r)[29]), "=r"((r)[30]), "=r"((r)[31]) \
        : "r"(tmem_addr))

// SS-form cg1 kind::f16 MMA (bf16 inputs per idesc), fp32 accumulate in TMEM
__device__ __forceinline__ void mma_f16_ss(uint32_t d_tmem, uint64_t a_desc,
                                           uint64_t b_desc, uint32_t idesc,
                                           uint32_t enable) {
    asm volatile(
        "{ .reg .pred p; setp.ne.u32 p, %4, 0;\n\t"
        "tcgen05.mma.cta_group::1.kind::f16 [%0], %1, %2, %3, {%5,%5,%5,%5}, p;\n\t}"
        :: "r"(d_tmem), "l"(a_desc), "l"(b_desc), "r"(idesc), "r"(enable), "r"(0u)
        : "memory");
}
#endif // HAS_TCGEN05

#define SWZ(o) ((uint32_t)(o) ^ ((((uint32_t)(o)) >> 3) & 0x70u))

// SW128 K-major smem descriptor: LBO=1, SBO=64, version=1, layout=SW128
static __device__ __forceinline__ uint64_t make_desc(uint32_t addr) {
    const uint64_t base = (uint64_t(2) << 61) | (uint64_t(1) << 46) |
                          (uint64_t(64) << 32) | (uint64_t(1) << 16);
    return base | ((uint64_t)(addr >> 4) & 0x3FFFu);
}

// ---------------------------------------------------------------------------
// GEMM: out[M=4096, N=1024] = X[4096,1024] @ W[1024,1024]^T + bias
// Fast path (sm_103a cubin): tcgen05, 128x128 CTA tile, K chunks of 64,
// bf16x3 (hi/lo) decomposition, double-buffered smem, fp32 accum in TMEM.
// Fallback (compute_103 PTX pass): round-1 fp32 SGEMM, same grid/block.
// ---------------------------------------------------------------------------
__global__ void __launch_bounds__(256, 1)
gemm_tc(const float* __restrict__ X, const float* __restrict__ W,
        const float* __restrict__ bias, float* __restrict__ out)
{
#if HAS_TCGEN05
    extern __shared__ char smc[];
    const uint32_t sb  = smem_u32(smc);
    const int tid = threadIdx.x;
    const int wid = tid >> 5, lid = tid & 31;
    const int m0 = blockIdx.y * 128;
    const int n0 = blockIdx.x * 128;

    // smem map: [0:4) tmem ptr, [8:24) mbarriers x2, tiles from 1024
    // buffer b at 1024 + b*65536: A_hi(16K) A_lo(16K) B_hi(16K) B_lo(16K)
    if (tid == 0) { MBAR_INIT(sb + 8, 1); MBAR_INIT(sb + 16, 1); }
    if (wid == 0) { TC_ALLOC(sb, 128); TC_RELINQ(); }
    __syncthreads();
    uint32_t tmem;
    asm("ld.shared.b32 %0, [%1];" : "=r"(tmem) : "r"(sb));

    // idesc: dtype F32, atype/btype BF16, N=128 (16<<17), M=128 (8<<24)
    const uint32_t idesc = (1u << 4) | (1u << 7) | (1u << 10) | (16u << 17) | (8u << 24);

    for (int ch = 0; ch < 16; ch++) {
        const int buf = ch & 1;
        const uint32_t tb = 1024u + (uint32_t)buf * 65536u;
        if (ch >= 2) {            // wait: MMA of chunk ch-2 done with this buffer
            MBAR_WAIT(sb + 8 + buf * 8, ((ch - 2) >> 1) & 1);
        }
        const int k0 = ch * 64;

        // Load 128x64 fp32 of X and W, split into bf16 hi/lo, store swizzled
#pragma unroll
        for (int i = 0; i < 8; i++) {
            const int idx = i * 256 + tid;        // 0..2047 float4 slots
            const int row = idx >> 4;
            const int c4  = idx & 15;
            const uint32_t so = SWZ(row * 128 + c4 * 8);

            float4 f = *(const float4*)&X[(size_t)(m0 + row) * DMODEL + k0 + c4 * 4];
            __nv_bfloat162 h0 = __floats2bfloat162_rn(f.x, f.y);
            __nv_bfloat162 h1 = __floats2bfloat162_rn(f.z, f.w);
            float2 hf0 = __bfloat1622float2(h0), hf1 = __bfloat1622float2(h1);
            __nv_bfloat162 l0 = __floats2bfloat162_rn(f.x - hf0.x, f.y - hf0.y);
            __nv_bfloat162 l1 = __floats2bfloat162_rn(f.z - hf1.x, f.w - hf1.y);
            uint2 hv, lv;
            hv.x = *reinterpret_cast<uint32_t*>(&h0); hv.y = *reinterpret_cast<uint32_t*>(&h1);
            lv.x = *reinterpret_cast<uint32_t*>(&l0); lv.y = *reinterpret_cast<uint32_t*>(&l1);
            *(uint2*)(smc + tb + so)           = hv;  // A_hi
            *(uint2*)(smc + tb + 16384 + so)   = lv;  // A_lo

            float4 g = *(const float4*)&W[(size_t)(n0 + row) * DMODEL + k0 + c4 * 4];
            __nv_bfloat162 g0 = __floats2bfloat162_rn(g.x, g.y);
            __nv_bfloat162 g1 = __floats2bfloat162_rn(g.z, g.w);
            float2 gf0 = __bfloat1622float2(g0), gf1 = __bfloat1622float2(g1);
            __nv_bfloat162 m0v = __floats2bfloat162_rn(g.x - gf0.x, g.y - gf0.y);
            __nv_bfloat162 m1v = __floats2bfloat162_rn(g.z - gf1.x, g.w - gf1.y);
            uint2 gv, mv;
            gv.x = *reinterpret_cast<uint32_t*>(&g0); gv.y = *reinterpret_cast<uint32_t*>(&g1);
            mv.x = *reinterpret_cast<uint32_t*>(&m0v); mv.y = *reinterpret_cast<uint32_t*>(&m1v);
            *(uint2*)(smc + tb + 32768 + so) = gv;  // B_hi
            *(uint2*)(smc + tb + 49152 + so) = mv;  // B_lo
        }
        __syncthreads();

        if (wid == 0 && elect_one()) {
            asm volatile("fence.proxy.async.shared::cta;" ::: "memory");
            const uint64_t dAh = make_desc(sb + tb);
            const uint64_t dAl = make_desc(sb + tb + 16384);
            const uint64_t dBh = make_desc(sb + tb + 32768);
            const uint64_t dBl = make_desc(sb + tb + 49152);
            // pass 0: Ahi*Bhi, pass 1: Ahi*Blo, pass 2: Alo*Bhi
#pragma unroll
            for (int ks = 0; ks < 4; ks++)
                mma_f16_ss(tmem, dAh + ks * 2, dBh + ks * 2, idesc,
                           (ch == 0 && ks == 0) ? 0u : 1u);
#pragma unroll
            for (int ks = 0; ks < 4; ks++)
                mma_f16_ss(tmem, dAh + ks * 2, dBl + ks * 2, idesc, 1u);
#pragma unroll
            for (int ks = 0; ks < 4; ks++)
                mma_f16_ss(tmem, dAl + ks * 2, dBh + ks * 2, idesc, 1u);
            TC_COMMIT(sb + 8 + buf * 8);
        }
    }

    // Final wait: buffer 1 (chunk 15) commit covers all prior MMAs (in-order pipe)
    MBAR_WAIT(sb + 16, 1);
    TC_FENCE_AFTER();

    if (wid < 4) {
        const int m = m0 + wid * 32 + lid;
#pragma unroll
        for (int c0 = 0; c0 < 128; c0 += 32) {
            uint32_t r[32];
            TC_LD_X32(r, tmem + c0);
            TC_WAIT_LD();
#pragma unroll
            for (int j = 0; j < 32; j += 4) {
                float4 bv = *(const float4*)&bias[n0 + c0 + j];
                float4 o;
                o.x = __uint_as_float(r[j + 0]) + bv.x;
                o.y = __uint_as_float(r[j + 1]) + bv.y;
                o.z = __uint_as_float(r[j + 2]) + bv.z;
                o.w = __uint_as_float(r[j + 3]) + bv.w;
                *(float4*)&out[(size_t)m * DMODEL + n0 + c0 + j] = o;
            }
        }
    }
    __syncthreads();
    if (wid == 0) TC_DEALLOC(tmem, 128);

#else  // ---------------- fp32 fallback (compute_103 PTX pass) --------------
    extern __shared__ char smc[];
    float* As = (float*)smc;            // [8][128]
    float* Bs = As + 8 * 128;           // [8][128]

    const int tid  = threadIdx.x;
    const int m0   = blockIdx.y * 128;
    const int n0   = blockIdx.x * 128;
    const int tx   = tid & 15;
    const int ty   = tid >> 4;
    const int lrow = tid >> 1;
    const int lc   = (tid & 1) * 4;

    const float* Xp = X + (size_t)(m0 + lrow) * DMODEL + lc;
    const float* Wp = W + (size_t)(n0 + lrow) * DMODEL + lc;

    float acc[8][8];
#pragma unroll
    for (int i = 0; i < 8; i++)
#pragma unroll
        for (int j = 0; j < 8; j++) acc[i][j] = 0.0f;

    for (int k0 = 0; k0 < DMODEL; k0 += 8) {
        float4 av = *(const float4*)(Xp + k0);
        float4 bv = *(const float4*)(Wp + k0);
        __syncthreads();
        As[(lc + 0) * 128 + lrow] = av.x; As[(lc + 1) * 128 + lrow] = av.y;
        As[(lc + 2) * 128 + lrow] = av.z; As[(lc + 3) * 128 + lrow] = av.w;
        Bs[(lc + 0) * 128 + lrow] = bv.x; Bs[(lc + 1) * 128 + lrow] = bv.y;
        Bs[(lc + 2) * 128 + lrow] = bv.z; Bs[(lc + 3) * 128 + lrow] = bv.w;
        __syncthreads();
#pragma unroll
        for (int kk = 0; kk < 8; kk++) {
            float a[8], b[8];
            *(float4*)&a[0] = *(const float4*)&As[kk * 128 + ty * 8];
            *(float4*)&a[4] = *(const float4*)&As[kk * 128 + ty * 8 + 4];
            *(float4*)&b[0] = *(const float4*)&Bs[kk * 128 + tx * 8];
            *(float4*)&b[4] = *(const float4*)&Bs[kk * 128 + tx * 8 + 4];
#pragma unroll
            for (int i = 0; i < 8; i++)
#pragma unroll
                for (int j = 0; j < 8; j++)
                    acc[i][j] = fmaf(a[i], b[j], acc[i][j]);
        }
    }

#pragma unroll
    for (int i = 0; i < 8; i++) {
        const int m = m0 + ty * 8 + i;
#pragma unroll
        for (int j = 0; j < 8; j++) {
            const int n = n0 + tx * 8 + j;
            out[(size_t)m * DMODEL + n] = acc[i][j] + bias[n];
        }
    }
#endif
}

// ---------------------------------------------------------------------------
// Flash attention (fp32) — reads Q/K/V from the row-major [m][n] projection
// outputs: row m = s*NB + b, cols h*64..h*64+63.
// ---------------------------------------------------------------------------
__global__ void __launch_bounds__(256)
flash_kernel(float* __restrict__ Og)
{
    extern __shared__ float sm[];
    float* Qs = sm;                 // [d=64][PAD]  Qs[d][q]
    float* Ks = Qs + 64 * PAD;      // [d=64][PAD]  Ks[d][k]
    float* Vs = Ks + 64 * PAD;      // [k=64][PAD]  Vs[k][d]
    float* Ps = Vs + 64 * PAD;      // [k=64][PAD]  Ps[k][q]

    const int tid = threadIdx.x;
    const int tx  = tid & 15;
    const int ty  = tid >> 4;
    const int bh  = blockIdx.y;             // b*NHEAD + h
    const int q0  = blockIdx.x * 64;
    const int bb  = bh >> 4;
    const int hh  = bh & 15;
    const size_t colbase = (size_t)hh * DKH;

    for (int i = tid; i < 64 * 64; i += 256) {
        const int r = i >> 6, c = i & 63;
        Qs[c * PAD + r] =
            g_Q[((size_t)(q0 + r) * NB + bb) * DMODEL + colbase + c] * 0.125f;
    }

    float mrun[4], lrun[4], o[4][4];
#pragma unroll
    for (int i = 0; i < 4; i++) {
        mrun[i] = -1e30f; lrun[i] = 0.0f;
#pragma unroll
        for (int j = 0; j < 4; j++) o[i][j] = 0.0f;
    }

    for (int kt = 0; kt < S_LEN; kt += 64) {
        __syncthreads();
        for (int i = tid; i < 64 * 64; i += 256) {
            const int r = i >> 6, c = i & 63;
            Ks[c * PAD + r] =
                g_K[((size_t)(kt + r) * NB + bb) * DMODEL + colbase + c];
        }
        for (int i = tid; i < 64 * 16; i += 256) {
            const int r = i >> 4, c4 = i & 15;
            *(float4*)&Vs[r * PAD + c4 * 4] =
                *(const float4*)&g_V[((size_t)(kt + r) * NB + bb) * DMODEL + colbase + c4 * 4];
        }
        __syncthreads();

        float s[4][4];
#pragma unroll
        for (int i = 0; i < 4; i++)
#pragma unroll
            for (int j = 0; j < 4; j++) s[i][j] = 0.0f;

#pragma unroll 4
        for (int d = 0; d < 64; d++) {
            float a[4], b[4];
            *(float4*)a = *(const float4*)&Qs[d * PAD + ty * 4];
            *(float4*)b = *(const float4*)&Ks[d * PAD + tx * 4];
#pragma unroll
            for (int i = 0; i < 4; i++)
#pragma unroll
                for (int j = 0; j < 4; j++)
                    s[i][j] = fmaf(a[i], b[j], s[i][j]);
        }

#pragma unroll
        for (int i = 0; i < 4; i++) {
            float mx = fmaxf(fmaxf(s[i][0], s[i][1]), fmaxf(s[i][2], s[i][3]));
#pragma unroll
            for (int off = 8; off > 0; off >>= 1)
                mx = fmaxf(mx, __shfl_xor_sync(0xffffffffu, mx, off, 16));
            const float mnew  = fmaxf(mrun[i], mx);
            const float alpha = __expf(mrun[i] - mnew);
            mrun[i] = mnew;
            float rs = 0.0f;
#pragma unroll
            for (int j = 0; j < 4; j++) {
                s[i][j] = __expf(s[i][j] - mnew);
                rs += s[i][j];
            }
#pragma unroll
            for (int off = 8; off > 0; off >>= 1)
                rs += __shfl_xor_sync(0xffffffffu, rs, off, 16);
            lrun[i] = lrun[i] * alpha + rs;
#pragma unroll
            for (int j = 0; j < 4; j++) o[i][j] *= alpha;
        }

#pragma unroll
        for (int j = 0; j < 4; j++)
#pragma unroll
            for (int i = 0; i < 4; i++)
                Ps[(tx * 4 + j) * PAD + ty * 4 + i] = s[i][j];
        __syncthreads();

#pragma unroll 4
        for (int k = 0; k < 64; k++) {
            float a[4], b[4];
            *(float4*)a = *(const float4*)&Ps[k * PAD + ty * 4];
            *(float4*)b = *(const float4*)&Vs[k * PAD + tx * 4];
#pragma unroll
            for (int i = 0; i < 4; i++)
#pragma unroll
                for (int j = 0; j < 4; j++)
                    o[i][j] = fmaf(a[i], b[j], o[i][j]);
        }
    }

#pragma unroll
    for (int i = 0; i < 4; i++) {
        const float inv = 1.0f / lrun[i];
        const int qg = q0 + ty * 4 + i;
        float4 v = make_float4(o[i][0] * inv, o[i][1] * inv,
                               o[i][2] * inv, o[i][3] * inv);
        *(float4*)&Og[((size_t)qg * NB + bb) * DMODEL + colbase + tx * 4] = v;
    }
}

// ---------------------------------------------------------------------------
extern "C" void kernel_launch(void* const* d_in, const int* in_sizes, int n_in,
                              void* d_out, int out_size)
{
    const float* q  = (const float*)d_in[0];
    const float* k  = (const float*)d_in[1];
    const float* v  = (const float*)d_in[2];
    const float* Wq = (const float*)d_in[3];
    const float* bq = (const float*)d_in[4];
    const float* Wk = (const float*)d_in[5];
    const float* bk = (const float*)d_in[6];
    const float* Wv = (const float*)d_in[7];
    const float* bv = (const float*)d_in[8];
    const float* Wo = (const float*)d_in[9];
    const float* bo = (const float*)d_in[10];
    float* out = (float*)d_out;

    float *gq, *gk, *gv, *gao;
    cudaGetSymbolAddress((void**)&gq,  g_Q);
    cudaGetSymbolAddress((void**)&gk,  g_K);
    cudaGetSymbolAddress((void**)&gv,  g_V);
    cudaGetSymbolAddress((void**)&gao, g_AO);

    const int gsmem = 1024 + 2 * 65536;   // 132,096 B (fast path; fallback uses a slice)
    cudaFuncSetAttribute(gemm_tc,
                         cudaFuncAttributeMaxDynamicSharedMemorySize, gsmem);
    cudaFuncSetAttribute(flash_kernel,
                         cudaFuncAttributeMaxDynamicSharedMemorySize,
                         (int)(4 * 64 * PAD * sizeof(float)));

    const dim3 ggrid(DMODEL / 128, MROWS / 128);   // (8, 32)

    gemm_tc<<<ggrid, 256, gsmem>>>(q, Wq, bq, gq);
    gemm_tc<<<ggrid, 256, gsmem>>>(k, Wk, bk, gk);
    gemm_tc<<<ggrid, 256, gsmem>>>(v, Wv, bv, gv);

    const size_t fsmem = 4 * 64 * PAD * sizeof(float);   // 69,632 B
    flash_kernel<<<dim3(S_LEN / 64, NB * NHEAD), 256, fsmem>>>(gao);

    gemm_tc<<<ggrid, 256, gsmem>>>(gao, Wo, bo, out);
}

// round 4
// speedup vs baseline: 4.6878x; 3.0763x over previous
#include <cuda_runtime.h>
#include <cuda_bf16.h>
#include <cstdint>

#define S_LEN   2048
#define NB      2
#define DMODEL  1024
#define NHEAD   16
#define DKH     64
#define MROWS   (S_LEN * NB)   // 4096

#if defined(__CUDA_ARCH_FEAT_SM103_ALL) || defined(__CUDA_ARCH_FEAT_SM100_ALL)
#define HAS_TCGEN05 1
#else
#define HAS_TCGEN05 0
#endif

// Scratch: Q/K/V and attention output, all row-major [m][n] = [4096][1024]
__device__ float g_Q [MROWS * DMODEL];
__device__ float g_K [MROWS * DMODEL];
__device__ float g_V [MROWS * DMODEL];
__device__ float g_AO[MROWS * DMODEL];

// ---------------------------------------------------------------------------
// PTX helpers
// ---------------------------------------------------------------------------
__device__ __forceinline__ uint32_t smem_u32(const void* p) {
    uint32_t a;
    asm("{ .reg .u64 t; cvta.to.shared.u64 t, %1; cvt.u32.u64 %0, t; }"
        : "=r"(a) : "l"(p));
    return a;
}
__device__ __forceinline__ uint32_t elect_one() {
    uint32_t p;
    asm volatile("{ .reg .pred p; elect.sync _|p, 0xFFFFFFFF; selp.b32 %0,1,0,p; }"
                 : "=r"(p));
    return p;
}

#define MBAR_INIT(addr, cnt) \
    asm volatile("mbarrier.init.shared.b64 [%0], %1;" :: "r"(addr), "r"(cnt) : "memory")

#define MBAR_WAIT(addr, parity) do {                                          \
    uint32_t _m = (addr); uint32_t _p = (parity); uint32_t _d;                \
    asm volatile("{ .reg .pred p; mbarrier.try_wait.parity.acquire.cta.shared::cta.b64 p, [%1], %2;" \
                 " selp.b32 %0,1,0,p; }" : "=r"(_d) : "r"(_m), "r"(_p) : "memory"); \
    if (!_d) {                                                                \
        asm volatile("{ .reg .pred P1; WL_%=:"                                \
                     " mbarrier.try_wait.parity.acquire.cta.shared::cta.b64 P1, [%0], %1, 0x989680;" \
                     " @P1 bra.uni WD_%=; bra.uni WL_%=; WD_%=: }"            \
                     :: "r"(_m), "r"(_p) : "memory");                         \
    }                                                                         \
} while (0)

#if HAS_TCGEN05
#define TC_ALLOC(smem_addr, ncols) \
    asm volatile("tcgen05.alloc.cta_group::1.sync.aligned.shared::cta.b32 [%0], %1;" \
                 :: "r"(smem_addr), "r"(ncols) : "memory")
#define TC_RELINQ() \
    asm volatile("tcgen05.relinquish_alloc_permit.cta_group::1.sync.aligned;")
#define TC_DEALLOC(tmem, ncols) \
    asm volatile("tcgen05.dealloc.cta_group::1.sync.aligned.b32 %0, %1;" :: "r"(tmem), "r"(ncols))
#define TC_COMMIT(mbar) \
    asm volatile("tcgen05.commit.cta_group::1.mbarrier::arrive::one.shared::cluster.b64 [%0];" \
                 :: "r"(mbar) : "memory")
#define TC_FENCE_AFTER()   asm volatile("tcgen05.fence::after_thread_sync;" ::: "memory")
#define TC_FENCE_BEFORE()  asm volatile("tcgen05.fence::before_thread_sync;" ::: "memory")
#define TC_WAIT_LD()       asm volatile("tcgen05.wait::ld.sync.aligned;" ::: "memory")
#define TC_WAIT_ST()       asm volatile("tcgen05.wait::st.sync.aligned;" ::: "memory")

#define TC_LD_X32(r, tmem_addr) \
    asm volatile( \
        "tcgen05.ld.sync.aligned.32x32b.x32.b32 " \
        "{%0, %1, %2, %3, %4, %5, %6, %7, %8, %9, %10, %11, %12, %13, %14, %15, " \
        " %16, %17, %18, %19, %20, %21, %22, %23, %24, %25, %26, %27, %28, %29, %30, %31}, [%32];" \
        : "=r"((r)[0]),  "=r"((r)[1]),  "=r"((r)[2]),  "=r"((r)[3]), \
          "=r"((r)[4]),  "=r"((r)[5]),  "=r"((r)[6]),  "=r"((r)[7]), \
          "=r"((r)[8]),  "=r"((r)[9]),  "=r"((r)[10]), "=r"((r)[11]), \
          "=r"((r)[12]), "=r"((r)[13]), "=r"((r)[14]), "=r"((r)[15]), \
          "=r"((r)[16]), "=r"((r)[17]), "=r"((r)[18]), "=r"((r)[19]), \
          "=r"((r)[20]), "=r"((r)[21]), "=r"((r)[22]), "=r"((r)[23]), \
          "=r"((r)[24]), "=r"((r)[25]), "=r"((r)[26]), "=r"((r)[27]), \
          "=r"((r)[28]), "=r"((r)[29]), "=r"((r)[30]), "=r"((r)[31]) \
        : "r"(tmem_addr))

#define TC_ST_X32(tmem_addr, r) \
    asm volatile( \
        "tcgen05.st.sync.aligned.32x32b.x32.b32 [%0], " \
        "{%1, %2, %3, %4, %5, %6, %7, %8, %9, %10, %11, %12, %13, %14, %15, %16, " \
        " %17, %18, %19, %20, %21, %22, %23, %24, %25, %26, %27, %28, %29, %30, %31, %32};" \
        :: "r"(tmem_addr), \
           "r"((r)[0]),  "r"((r)[1]),  "r"((r)[2]),  "r"((r)[3]), \
           "r"((r)[4]),  "r"((r)[5]),  "r"((r)[6]),  "r"((r)[7]), \
           "r"((r)[8]),  "r"((r)[9]),  "r"((r)[10]), "r"((r)[11]), \
           "r"((r)[12]), "r"((r)[13]), "r"((r)[14]), "r"((r)[15]), \
           "r"((r)[16]), "r"((r)[17]), "r"((r)[18]), "r"((r)[19]), \
           "r"((r)[20]), "r"((r)[21]), "r"((r)[22]), "r"((r)[23]), \
           "r"((r)[24]), "r"((r)[25]), "r"((r)[26]), "r"((r)[27]), \
           "r"((r)[28]), "r"((r)[29]), "r"((r)[30]), "r"((r)[31]) \
        : "memory")

// SS-form cg1 kind::f16 MMA (bf16 inputs per idesc), fp32 accumulate in TMEM
__device__ __forceinline__ void mma_f16_ss(uint32_t d_tmem, uint64_t a_desc,
                                           uint64_t b_desc, uint32_t idesc,
                                           uint32_t enable) {
    asm volatile(
        "{ .reg .pred p; setp.ne.u32 p, %4, 0;\n\t"
        "tcgen05.mma.cta_group::1.kind::f16 [%0], %1, %2, %3, {%5,%5,%5,%5}, p;\n\t}"
        :: "r"(d_tmem), "l"(a_desc), "l"(b_desc), "r"(idesc), "r"(enable), "r"(0u)
        : "memory");
}

// TS-form cg1 kind::f16 MMA: A in TMEM (bf16x2 per col), B in smem
__device__ __forceinline__ void mma_f16_ts(uint32_t d_tmem, uint32_t a_tmem,
                                           uint64_t b_desc, uint32_t idesc,
                                           uint32_t enable) {
    asm volatile(
        "{ .reg .pred p; setp.ne.u32 p, %4, 0;\n\t"
        "tcgen05.mma.cta_group::1.kind::f16 [%0], [%1], %2, %3, {%5,%5,%5,%5}, p;\n\t}"
        :: "r"(d_tmem), "r"(a_tmem), "l"(b_desc), "r"(idesc), "r"(enable), "r"(0u)
        : "memory");
}
#endif // HAS_TCGEN05

#define SWZ(o) ((uint32_t)(o) ^ ((((uint32_t)(o)) >> 3) & 0x70u))

// SW128 K-major smem descriptor: LBO=1, SBO=64, version=1, layout=SW128
static __device__ __forceinline__ uint64_t make_desc(uint32_t addr) {
    const uint64_t base = (uint64_t(2) << 61) | (uint64_t(1) << 46) |
                          (uint64_t(64) << 32) | (uint64_t(1) << 16);
    return base | ((uint64_t)(addr >> 4) & 0x3FFFu);
}

// ---------------------------------------------------------------------------
// GEMM: out[M=4096, N=1024] = X[4096,1024] @ W[1024,1024]^T + bias
// (unchanged from round 3 — tcgen05 bf16x3 fast path, fp32 fallback)
// ---------------------------------------------------------------------------
__global__ void __launch_bounds__(256, 1)
gemm_tc(const float* __restrict__ X, const float* __restrict__ W,
        const float* __restrict__ bias, float* __restrict__ out)
{
#if HAS_TCGEN05
    extern __shared__ char smc[];
    const uint32_t sb  = smem_u32(smc);
    const int tid = threadIdx.x;
    const int wid = tid >> 5, lid = tid & 31;
    const int m0 = blockIdx.y * 128;
    const int n0 = blockIdx.x * 128;

    if (tid == 0) { MBAR_INIT(sb + 8, 1); MBAR_INIT(sb + 16, 1); }
    if (wid == 0) { TC_ALLOC(sb, 128); TC_RELINQ(); }
    __syncthreads();
    uint32_t tmem;
    asm("ld.shared.b32 %0, [%1];" : "=r"(tmem) : "r"(sb));

    const uint32_t idesc = (1u << 4) | (1u << 7) | (1u << 10) | (16u << 17) | (8u << 24);

    for (int ch = 0; ch < 16; ch++) {
        const int buf = ch & 1;
        const uint32_t tb = 1024u + (uint32_t)buf * 65536u;
        if (ch >= 2) MBAR_WAIT(sb + 8 + buf * 8, ((ch - 2) >> 1) & 1);
        const int k0 = ch * 64;

#pragma unroll
        for (int i = 0; i < 8; i++) {
            const int idx = i * 256 + tid;
            const int row = idx >> 4;
            const int c4  = idx & 15;
            const uint32_t so = SWZ(row * 128 + c4 * 8);

            float4 f = *(const float4*)&X[(size_t)(m0 + row) * DMODEL + k0 + c4 * 4];
            __nv_bfloat162 h0 = __floats2bfloat162_rn(f.x, f.y);
            __nv_bfloat162 h1 = __floats2bfloat162_rn(f.z, f.w);
            float2 hf0 = __bfloat1622float2(h0), hf1 = __bfloat1622float2(h1);
            __nv_bfloat162 l0 = __floats2bfloat162_rn(f.x - hf0.x, f.y - hf0.y);
            __nv_bfloat162 l1 = __floats2bfloat162_rn(f.z - hf1.x, f.w - hf1.y);
            uint2 hv, lv;
            hv.x = *reinterpret_cast<uint32_t*>(&h0); hv.y = *reinterpret_cast<uint32_t*>(&h1);
            lv.x = *reinterpret_cast<uint32_t*>(&l0); lv.y = *reinterpret_cast<uint32_t*>(&l1);
            *(uint2*)(smc + tb + so)           = hv;
            *(uint2*)(smc + tb + 16384 + so)   = lv;

            float4 g = *(const float4*)&W[(size_t)(n0 + row) * DMODEL + k0 + c4 * 4];
            __nv_bfloat162 g0 = __floats2bfloat162_rn(g.x, g.y);
            __nv_bfloat162 g1 = __floats2bfloat162_rn(g.z, g.w);
            float2 gf0 = __bfloat1622float2(g0), gf1 = __bfloat1622float2(g1);
            __nv_bfloat162 m0v = __floats2bfloat162_rn(g.x - gf0.x, g.y - gf0.y);
            __nv_bfloat162 m1v = __floats2bfloat162_rn(g.z - gf1.x, g.w - gf1.y);
            uint2 gv, mv;
            gv.x = *reinterpret_cast<uint32_t*>(&g0); gv.y = *reinterpret_cast<uint32_t*>(&g1);
            mv.x = *reinterpret_cast<uint32_t*>(&m0v); mv.y = *reinterpret_cast<uint32_t*>(&m1v);
            *(uint2*)(smc + tb + 32768 + so) = gv;
            *(uint2*)(smc + tb + 49152 + so) = mv;
        }
        __syncthreads();

        if (wid == 0 && elect_one()) {
            asm volatile("fence.proxy.async.shared::cta;" ::: "memory");
            const uint64_t dAh = make_desc(sb + tb);
            const uint64_t dAl = make_desc(sb + tb + 16384);
            const uint64_t dBh = make_desc(sb + tb + 32768);
            const uint64_t dBl = make_desc(sb + tb + 49152);
#pragma unroll
            for (int ks = 0; ks < 4; ks++)
                mma_f16_ss(tmem, dAh + ks * 2, dBh + ks * 2, idesc,
                           (ch == 0 && ks == 0) ? 0u : 1u);
#pragma unroll
            for (int ks = 0; ks < 4; ks++)
                mma_f16_ss(tmem, dAh + ks * 2, dBl + ks * 2, idesc, 1u);
#pragma unroll
            for (int ks = 0; ks < 4; ks++)
                mma_f16_ss(tmem, dAl + ks * 2, dBh + ks * 2, idesc, 1u);
            TC_COMMIT(sb + 8 + buf * 8);
        }
    }

    MBAR_WAIT(sb + 16, 1);
    TC_FENCE_AFTER();

    if (wid < 4) {
        const int m = m0 + wid * 32 + lid;
#pragma unroll
        for (int c0 = 0; c0 < 128; c0 += 32) {
            uint32_t r[32];
            TC_LD_X32(r, tmem + c0);
            TC_WAIT_LD();
#pragma unroll
            for (int j = 0; j < 32; j += 4) {
                float4 bv = *(const float4*)&bias[n0 + c0 + j];
                float4 o;
                o.x = __uint_as_float(r[j + 0]) + bv.x;
                o.y = __uint_as_float(r[j + 1]) + bv.y;
                o.z = __uint_as_float(r[j + 2]) + bv.z;
                o.w = __uint_as_float(r[j + 3]) + bv.w;
                *(float4*)&out[(size_t)m * DMODEL + n0 + c0 + j] = o;
            }
        }
    }
    __syncthreads();
    if (wid == 0) TC_DEALLOC(tmem, 128);

#else  // ---------------- fp32 fallback (compute_103 PTX pass) --------------
    extern __shared__ char smc[];
    float* As = (float*)smc;
    float* Bs = As + 8 * 128;

    const int tid  = threadIdx.x;
    const int m0   = blockIdx.y * 128;
    const int n0   = blockIdx.x * 128;
    const int tx   = tid & 15;
    const int ty   = tid >> 4;
    const int lrow = tid >> 1;
    const int lc   = (tid & 1) * 4;

    const float* Xp = X + (size_t)(m0 + lrow) * DMODEL + lc;
    const float* Wp = W + (size_t)(n0 + lrow) * DMODEL + lc;

    float acc[8][8];
#pragma unroll
    for (int i = 0; i < 8; i++)
#pragma unroll
        for (int j = 0; j < 8; j++) acc[i][j] = 0.0f;

    for (int k0 = 0; k0 < DMODEL; k0 += 8) {
        float4 av = *(const float4*)(Xp + k0);
        float4 bv = *(const float4*)(Wp + k0);
        __syncthreads();
        As[(lc + 0) * 128 + lrow] = av.x; As[(lc + 1) * 128 + lrow] = av.y;
        As[(lc + 2) * 128 + lrow] = av.z; As[(lc + 3) * 128 + lrow] = av.w;
        Bs[(lc + 0) * 128 + lrow] = bv.x; Bs[(lc + 1) * 128 + lrow] = bv.y;
        Bs[(lc + 2) * 128 + lrow] = bv.z; Bs[(lc + 3) * 128 + lrow] = bv.w;
        __syncthreads();
#pragma unroll
        for (int kk = 0; kk < 8; kk++) {
            float a[8], b[8];
            *(float4*)&a[0] = *(const float4*)&As[kk * 128 + ty * 8];
            *(float4*)&a[4] = *(const float4*)&As[kk * 128 + ty * 8 + 4];
            *(float4*)&b[0] = *(const float4*)&Bs[kk * 128 + tx * 8];
            *(float4*)&b[4] = *(const float4*)&Bs[kk * 128 + tx * 8 + 4];
#pragma unroll
            for (int i = 0; i < 8; i++)
#pragma unroll
                for (int j = 0; j < 8; j++)
                    acc[i][j] = fmaf(a[i], b[j], acc[i][j]);
        }
    }

#pragma unroll
    for (int i = 0; i < 8; i++) {
        const int m = m0 + ty * 8 + i;
#pragma unroll
        for (int j = 0; j < 8; j++) {
            const int n = n0 + tx * 8 + j;
            out[(size_t)m * DMODEL + n] = acc[i][j] + bias[n];
        }
    }
#endif
}

// ---------------------------------------------------------------------------
// tcgen05 flash attention.
// Grid (16, 32): x = q-tile of 128, y = b*NHEAD+h. 128 threads (4 warps).
// Per kk-tile (64 keys): S = Q Kt (SS, bf16x3) -> TMEM; LDTM S (thread owns
// one q row); online softmax in regs; P -> bf16 hi/lo -> STTM; PV delta (TS,
// 3 passes) -> TMEM; LDTM delta; O_reg = alpha*O_reg + delta.
// smem: QH 16K | QL 16K | KH 8K | KL 8K | VH 8K | VL 8K  (V stored [d][kk])
// TMEM: S @0 (64 cols) | delta @64 | Ph @128 (32) | Pl @160 (32); alloc 256.
// ---------------------------------------------------------------------------
#define FQH 1024u
#define FQL 17408u
#define FKH 33792u
#define FKL 41984u
#define FVH 50176u
#define FVL 58368u
#define FSMEM 66560

__global__ void __launch_bounds__(128, 1)
flash_tc(float* __restrict__ Og)
{
#if HAS_TCGEN05
    extern __shared__ char smc[];
    const uint32_t sb = smem_u32(smc);
    const int tid  = threadIdx.x;
    const int wid  = tid >> 5;
    const int lane = tid & 31;
    const int bh   = blockIdx.y;
    const int q0   = blockIdx.x * 128;
    const int bb   = bh >> 4;
    const int hh   = bh & 15;
    const size_t colbase = (size_t)hh * DKH;

    if (tid == 0) { MBAR_INIT(sb + 8, 1); MBAR_INIT(sb + 16, 1); }
    if (wid == 0) { TC_ALLOC(sb, 256); TC_RELINQ(); }
    __syncthreads();
    uint32_t tmem;
    asm("ld.shared.b32 %0, [%1];" : "=r"(tmem) : "r"(sb));

    // idesc: F32 accum, BF16 x BF16, N=64, M=128
    const uint32_t idesc = (1u << 4) | (1u << 7) | (1u << 10) | (8u << 17) | (8u << 24);

    // ---- Load Q tile (128 x 64), fold 0.125 scale, split bf16 hi/lo ----
#pragma unroll
    for (int i = 0; i < 16; i++) {
        const int idx = i * 128 + tid;       // 2048 float4 slots
        const int row = idx >> 4;
        const int c4  = idx & 15;
        const uint32_t so = SWZ(row * 128 + c4 * 8);
        float4 f = *(const float4*)&g_Q[((size_t)(q0 + row) * NB + bb) * DMODEL + colbase + c4 * 4];
        f.x *= 0.125f; f.y *= 0.125f; f.z *= 0.125f; f.w *= 0.125f;
        __nv_bfloat162 h0 = __floats2bfloat162_rn(f.x, f.y);
        __nv_bfloat162 h1 = __floats2bfloat162_rn(f.z, f.w);
        float2 hf0 = __bfloat1622float2(h0), hf1 = __bfloat1622float2(h1);
        __nv_bfloat162 l0 = __floats2bfloat162_rn(f.x - hf0.x, f.y - hf0.y);
        __nv_bfloat162 l1 = __floats2bfloat162_rn(f.z - hf1.x, f.w - hf1.y);
        uint2 hv, lv;
        hv.x = *reinterpret_cast<uint32_t*>(&h0); hv.y = *reinterpret_cast<uint32_t*>(&h1);
        lv.x = *reinterpret_cast<uint32_t*>(&l0); lv.y = *reinterpret_cast<uint32_t*>(&l1);
        *(uint2*)(smc + FQH + so) = hv;
        *(uint2*)(smc + FQL + so) = lv;
    }

    float o[64];
#pragma unroll
    for (int j = 0; j < 64; j++) o[j] = 0.0f;
    float mrun = -1e30f, lrun = 0.0f;

    const uint64_t dQh = make_desc(sb + FQH);
    const uint64_t dQl = make_desc(sb + FQL);
    const uint64_t dKh = make_desc(sb + FKH);
    const uint64_t dKl = make_desc(sb + FKL);
    const uint64_t dVh = make_desc(sb + FVH);
    const uint64_t dVl = make_desc(sb + FVL);
    const uint32_t warp_off = (uint32_t)wid << 21;

    for (int kt = 0; kt < 32; kt++) {
        const int k0 = kt * 64;
        const uint32_t par = kt & 1;

        // ---- Load K tile (64x64) hi/lo, and V tile transposed [d][kk] ----
#pragma unroll
        for (int i = 0; i < 8; i++) {
            const int idx = i * 128 + tid;     // 1024 float4 slots
            const int row = idx >> 4;          // kk 0..63
            const int c4  = idx & 15;          // d group
            const uint32_t so = SWZ(row * 128 + c4 * 8);
            float4 f = *(const float4*)&g_K[((size_t)(k0 + row) * NB + bb) * DMODEL + colbase + c4 * 4];
            __nv_bfloat162 h0 = __floats2bfloat162_rn(f.x, f.y);
            __nv_bfloat162 h1 = __floats2bfloat162_rn(f.z, f.w);
            float2 hf0 = __bfloat1622float2(h0), hf1 = __bfloat1622float2(h1);
            __nv_bfloat162 l0 = __floats2bfloat162_rn(f.x - hf0.x, f.y - hf0.y);
            __nv_bfloat162 l1 = __floats2bfloat162_rn(f.z - hf1.x, f.w - hf1.y);
            uint2 hv, lv;
            hv.x = *reinterpret_cast<uint32_t*>(&h0); hv.y = *reinterpret_cast<uint32_t*>(&h1);
            lv.x = *reinterpret_cast<uint32_t*>(&l0); lv.y = *reinterpret_cast<uint32_t*>(&l1);
            *(uint2*)(smc + FKH + so) = hv;
            *(uint2*)(smc + FKL + so) = lv;

            // V: read [kk][d0..d0+3], write transposed rows d, col kk (2B each)
            float4 g = *(const float4*)&g_V[((size_t)(k0 + row) * NB + bb) * DMODEL + colbase + c4 * 4];
            const float vv[4] = { g.x, g.y, g.z, g.w };
#pragma unroll
            for (int t = 0; t < 4; t++) {
                const int d = c4 * 4 + t;
                __nv_bfloat16 vh = __float2bfloat16_rn(vv[t]);
                __nv_bfloat16 vl = __float2bfloat16_rn(vv[t] - __bfloat162float(vh));
                const uint32_t vo = SWZ(d * 128 + row * 2);
                *(__nv_bfloat16*)(smc + FVH + vo) = vh;
                *(__nv_bfloat16*)(smc + FVL + vo) = vl;
            }
        }
        __syncthreads();

        // ---- S = Q * K^T (3 bf16 passes x 4 k-steps), into TMEM cols 0-63 ----
        if (wid == 0 && elect_one()) {
            asm volatile("fence.proxy.async.shared::cta;" ::: "memory");
#pragma unroll
            for (int ks = 0; ks < 4; ks++)
                mma_f16_ss(tmem, dQh + ks * 2, dKh + ks * 2, idesc, ks == 0 ? 0u : 1u);
#pragma unroll
            for (int ks = 0; ks < 4; ks++)
                mma_f16_ss(tmem, dQh + ks * 2, dKl + ks * 2, idesc, 1u);
#pragma unroll
            for (int ks = 0; ks < 4; ks++)
                mma_f16_ss(tmem, dQl + ks * 2, dKh + ks * 2, idesc, 1u);
            TC_COMMIT(sb + 8);
        }
        MBAR_WAIT(sb + 8, par);
        TC_FENCE_AFTER();

        // ---- LDTM S: this thread owns q row = wid*32+lane, cols 0..63 ----
        float s[64];
        {
            uint32_t r[32];
            TC_LD_X32(r, tmem);
            TC_WAIT_LD();
#pragma unroll
            for (int j = 0; j < 32; j++) s[j] = __uint_as_float(r[j]);
            TC_LD_X32(r, tmem + 32);
            TC_WAIT_LD();
#pragma unroll
            for (int j = 0; j < 32; j++) s[32 + j] = __uint_as_float(r[j]);
        }
        TC_FENCE_BEFORE();

        // ---- Online softmax (row fully in this thread) ----
        float mx = s[0];
#pragma unroll
        for (int j = 1; j < 64; j++) mx = fmaxf(mx, s[j]);
        const float mnew  = fmaxf(mrun, mx);
        const float alpha = __expf(mrun - mnew);
        mrun = mnew;
        float rs = 0.0f;
#pragma unroll
        for (int j = 0; j < 64; j++) {
            s[j] = __expf(s[j] - mnew);
            rs += s[j];
        }
        lrun = lrun * alpha + rs;
#pragma unroll
        for (int j = 0; j < 64; j++) o[j] *= alpha;

        // ---- P -> bf16 hi/lo, STTM to TMEM cols 128/160 ----
        {
            uint32_t ph[32], pl[32];
#pragma unroll
            for (int j = 0; j < 32; j++) {
                __nv_bfloat162 h = __floats2bfloat162_rn(s[2 * j], s[2 * j + 1]);
                float2 hf = __bfloat1622float2(h);
                __nv_bfloat162 l = __floats2bfloat162_rn(s[2 * j] - hf.x, s[2 * j + 1] - hf.y);
                ph[j] = *reinterpret_cast<uint32_t*>(&h);
                pl[j] = *reinterpret_cast<uint32_t*>(&l);
            }
            TC_ST_X32(tmem + 128 + warp_off, ph);
            TC_ST_X32(tmem + 160 + warp_off, pl);
            TC_WAIT_ST();
        }
        TC_FENCE_BEFORE();
        __syncthreads();

        // ---- delta = P * V (TS mode, 3 passes x 4 k-steps), TMEM cols 64-127 ----
        if (wid == 0 && elect_one()) {
            TC_FENCE_AFTER();
#pragma unroll
            for (int ks = 0; ks < 4; ks++)
                mma_f16_ts(tmem + 64, tmem + 128 + ks * 8, dVh + ks * 2, idesc,
                           ks == 0 ? 0u : 1u);
#pragma unroll
            for (int ks = 0; ks < 4; ks++)
                mma_f16_ts(tmem + 64, tmem + 128 + ks * 8, dVl + ks * 2, idesc, 1u);
#pragma unroll
            for (int ks = 0; ks < 4; ks++)
                mma_f16_ts(tmem + 64, tmem + 160 + ks * 8, dVh + ks * 2, idesc, 1u);
            TC_COMMIT(sb + 16);
        }
        MBAR_WAIT(sb + 16, par);
        TC_FENCE_AFTER();

        // ---- LDTM delta, accumulate ----
        {
            uint32_t r[32];
            TC_LD_X32(r, tmem + 64);
            TC_WAIT_LD();
#pragma unroll
            for (int j = 0; j < 32; j++) o[j] += __uint_as_float(r[j]);
            TC_LD_X32(r, tmem + 96);
            TC_WAIT_LD();
#pragma unroll
            for (int j = 0; j < 32; j++) o[32 + j] += __uint_as_float(r[j]);
        }
        TC_FENCE_BEFORE();
        __syncthreads();   // K/V smem + TMEM reuse safe for next iteration
    }

    // ---- Write O / lrun ----
    const float inv = 1.0f / lrun;
    const int qg = q0 + wid * 32 + lane;
    float* orow = &Og[((size_t)qg * NB + bb) * DMODEL + colbase];
#pragma unroll
    for (int j = 0; j < 64; j += 4) {
        float4 v = make_float4(o[j] * inv, o[j + 1] * inv, o[j + 2] * inv, o[j + 3] * inv);
        *(float4*)&orow[j] = v;
    }
    __syncthreads();
    if (wid == 0) TC_DEALLOC(tmem, 256);

#else  // ---------------- scalar fallback (compute_103 PTX pass) ------------
    const int tid = threadIdx.x;
    const int bh  = blockIdx.y;
    const int q0  = blockIdx.x * 128;
    const int bb  = bh >> 4;
    const int hh  = bh & 15;
    const size_t colbase = (size_t)hh * DKH;

    const int qg = q0 + tid;
    float qr[64];
#pragma unroll
    for (int d = 0; d < 64; d++)
        qr[d] = g_Q[((size_t)qg * NB + bb) * DMODEL + colbase + d] * 0.125f;

    float o[64];
#pragma unroll
    for (int d = 0; d < 64; d++) o[d] = 0.0f;
    float m = -1e30f, l = 0.0f;

    for (int kk = 0; kk < S_LEN; kk++) {
        const float* kr = &g_K[((size_t)kk * NB + bb) * DMODEL + colbase];
        float s = 0.0f;
        for (int d = 0; d < 64; d++) s = fmaf(qr[d], kr[d], s);
        const float mn = fmaxf(m, s);
        const float al = __expf(m - mn);
        const float p  = __expf(s - mn);
        m = mn; l = l * al + p;
        const float* vr = &g_V[((size_t)kk * NB + bb) * DMODEL + colbase];
        for (int d = 0; d < 64; d++) o[d] = o[d] * al + p * vr[d];
    }
    const float inv = 1.0f / l;
    for (int d = 0; d < 64; d++)
        Og[((size_t)qg * NB + bb) * DMODEL + colbase + d] = o[d] * inv;
#endif
}

// ---------------------------------------------------------------------------
extern "C" void kernel_launch(void* const* d_in, const int* in_sizes, int n_in,
                              void* d_out, int out_size)
{
    const float* q  = (const float*)d_in[0];
    const float* k  = (const float*)d_in[1];
    const float* v  = (const float*)d_in[2];
    const float* Wq = (const float*)d_in[3];
    const float* bq = (const float*)d_in[4];
    const float* Wk = (const float*)d_in[5];
    const float* bk = (const float*)d_in[6];
    const float* Wv = (const float*)d_in[7];
    const float* bv = (const float*)d_in[8];
    const float* Wo = (const float*)d_in[9];
    const float* bo = (const float*)d_in[10];
    float* out = (float*)d_out;

    float *gq, *gk, *gv, *gao;
    cudaGetSymbolAddress((void**)&gq,  g_Q);
    cudaGetSymbolAddress((void**)&gk,  g_K);
    cudaGetSymbolAddress((void**)&gv,  g_V);
    cudaGetSymbolAddress((void**)&gao, g_AO);

    const int gsmem = 1024 + 2 * 65536;   // 132,096 B
    cudaFuncSetAttribute(gemm_tc,
                         cudaFuncAttributeMaxDynamicSharedMemorySize, gsmem);
    cudaFuncSetAttribute(flash_tc,
                         cudaFuncAttributeMaxDynamicSharedMemorySize, FSMEM);

    const dim3 ggrid(DMODEL / 128, MROWS / 128);   // (8, 32)

    gemm_tc<<<ggrid, 256, gsmem>>>(q, Wq, bq, gq);
    gemm_tc<<<ggrid, 256, gsmem>>>(k, Wk, bk, gk);
    gemm_tc<<<ggrid, 256, gsmem>>>(v, Wv, bv, gv);

    flash_tc<<<dim3(S_LEN / 128, NB * NHEAD), 128, FSMEM>>>(gao);

    gemm_tc<<<ggrid, 256, gsmem>>>(gao, Wo, bo, out);
}

// round 5
// speedup vs baseline: 4.9153x; 1.0485x over previous
#include <cuda_runtime.h>
#include <cuda_bf16.h>
#include <cstdint>

#define S_LEN   2048
#define NB      2
#define DMODEL  1024
#define NHEAD   16
#define DKH     64
#define MROWS   (S_LEN * NB)   // 4096
#define PLANE   (S_LEN * DKH)  // 131072 elems per (b,h) plane

#if defined(__CUDA_ARCH_FEAT_SM103_ALL) || defined(__CUDA_ARCH_FEAT_SM100_ALL)
#define HAS_TCGEN05 1
#else
#define HAS_TCGEN05 0
#endif

// ---- bf16 hi/lo scratch ----------------------------------------------------
// converted inputs (row-major [m][1024], m = s*2+b)
__device__ __nv_bfloat16 g_qh[MROWS * DMODEL], g_ql[MROWS * DMODEL];
__device__ __nv_bfloat16 g_kh[MROWS * DMODEL], g_kl[MROWS * DMODEL];
__device__ __nv_bfloat16 g_vh[MROWS * DMODEL], g_vl[MROWS * DMODEL];
// converted weights (row-major [n][1024])
__device__ __nv_bfloat16 g_wqh[DMODEL * DMODEL], g_wql[DMODEL * DMODEL];
__device__ __nv_bfloat16 g_wkh[DMODEL * DMODEL], g_wkl[DMODEL * DMODEL];
__device__ __nv_bfloat16 g_wvh[DMODEL * DMODEL], g_wvl[DMODEL * DMODEL];
__device__ __nv_bfloat16 g_woh[DMODEL * DMODEL], g_wol[DMODEL * DMODEL];
// projection outputs: Q/K planar [bh][s][d], V planar transposed [bh][d][s]
__device__ __nv_bfloat16 g_Qh[32 * PLANE], g_Ql[32 * PLANE];
__device__ __nv_bfloat16 g_Kh[32 * PLANE], g_Kl[32 * PLANE];
__device__ __nv_bfloat16 g_Vth[32 * PLANE], g_Vtl[32 * PLANE];
// attention output, row-major [m][1024]
__device__ __nv_bfloat16 g_AOh[MROWS * DMODEL], g_AOl[MROWS * DMODEL];

// ---------------------------------------------------------------------------
// helpers
// ---------------------------------------------------------------------------
__device__ __forceinline__ uint32_t smem_u32(const void* p) {
    uint32_t a;
    asm("{ .reg .u64 t; cvta.to.shared.u64 t, %1; cvt.u32.u64 %0, t; }"
        : "=r"(a) : "l"(p));
    return a;
}
__device__ __forceinline__ uint32_t elect_one() {
    uint32_t p;
    asm volatile("{ .reg .pred p; elect.sync _|p, 0xFFFFFFFF; selp.b32 %0,1,0,p; }"
                 : "=r"(p));
    return p;
}
__device__ __forceinline__ uint32_t bf2_bits(__nv_bfloat162 v) {
    return *reinterpret_cast<uint32_t*>(&v);
}

#define MBAR_INIT(addr, cnt) \
    asm volatile("mbarrier.init.shared.b64 [%0], %1;" :: "r"(addr), "r"(cnt) : "memory")

#define MBAR_WAIT(addr, parity) do {                                          \
    uint32_t _m = (addr); uint32_t _p = (parity); uint32_t _d;                \
    asm volatile("{ .reg .pred p; mbarrier.try_wait.parity.acquire.cta.shared::cta.b64 p, [%1], %2;" \
                 " selp.b32 %0,1,0,p; }" : "=r"(_d) : "r"(_m), "r"(_p) : "memory"); \
    if (!_d) {                                                                \
        asm volatile("{ .reg .pred P1; WL_%=:"                                \
                     " mbarrier.try_wait.parity.acquire.cta.shared::cta.b64 P1, [%0], %1, 0x989680;" \
                     " @P1 bra.uni WD_%=; bra.uni WL_%=; WD_%=: }"            \
                     :: "r"(_m), "r"(_p) : "memory");                         \
    }                                                                         \
} while (0)

#if HAS_TCGEN05
#define TC_ALLOC(smem_addr, ncols) \
    asm volatile("tcgen05.alloc.cta_group::1.sync.aligned.shared::cta.b32 [%0], %1;" \
                 :: "r"(smem_addr), "r"(ncols) : "memory")
#define TC_RELINQ() \
    asm volatile("tcgen05.relinquish_alloc_permit.cta_group::1.sync.aligned;")
#define TC_DEALLOC(tmem, ncols) \
    asm volatile("tcgen05.dealloc.cta_group::1.sync.aligned.b32 %0, %1;" :: "r"(tmem), "r"(ncols))
#define TC_COMMIT(mbar) \
    asm volatile("tcgen05.commit.cta_group::1.mbarrier::arrive::one.shared::cluster.b64 [%0];" \
                 :: "r"(mbar) : "memory")
#define TC_FENCE_AFTER()   asm volatile("tcgen05.fence::after_thread_sync;" ::: "memory")
#define TC_FENCE_BEFORE()  asm volatile("tcgen05.fence::before_thread_sync;" ::: "memory")
#define TC_WAIT_LD()       asm volatile("tcgen05.wait::ld.sync.aligned;" ::: "memory")
#define TC_WAIT_ST()       asm volatile("tcgen05.wait::st.sync.aligned;" ::: "memory")

#define TC_LD_X32(r, tmem_addr) \
    asm volatile( \
        "tcgen05.ld.sync.aligned.32x32b.x32.b32 " \
        "{%0, %1, %2, %3, %4, %5, %6, %7, %8, %9, %10, %11, %12, %13, %14, %15, " \
        " %16, %17, %18, %19, %20, %21, %22, %23, %24, %25, %26, %27, %28, %29, %30, %31}, [%32];" \
        : "=r"((r)[0]),  "=r"((r)[1]),  "=r"((r)[2]),  "=r"((r)[3]), \
          "=r"((r)[4]),  "=r"((r)[5]),  "=r"((r)[6]),  "=r"((r)[7]), \
          "=r"((r)[8]),  "=r"((r)[9]),  "=r"((r)[10]), "=r"((r)[11]), \
          "=r"((r)[12]), "=r"((r)[13]), "=r"((r)[14]), "=r"((r)[15]), \
          "=r"((r)[16]), "=r"((r)[17]), "=r"((r)[18]), "=r"((r)[19]), \
          "=r"((r)[20]), "=r"((r)[21]), "=r"((r)[22]), "=r"((r)[23]), \
          "=r"((r)[24]), "=r"((r)[25]), "=r"((r)[26]), "=r"((r)[27]), \
          "=r"((r)[28]), "=r"((r)[29]), "=r"((r)[30]), "=r"((r)[31]) \
        : "r"(tmem_addr))

#define TC_ST_X32(tmem_addr, r) \
    asm volatile( \
        "tcgen05.st.sync.aligned.32x32b.x32.b32 [%0], " \
        "{%1, %2, %3, %4, %5, %6, %7, %8, %9, %10, %11, %12, %13, %14, %15, %16, " \
        " %17, %18, %19, %20, %21, %22, %23, %24, %25, %26, %27, %28, %29, %30, %31, %32};" \
        :: "r"(tmem_addr), \
           "r"((r)[0]),  "r"((r)[1]),  "r"((r)[2]),  "r"((r)[3]), \
           "r"((r)[4]),  "r"((r)[5]),  "r"((r)[6]),  "r"((r)[7]), \
           "r"((r)[8]),  "r"((r)[9]),  "r"((r)[10]), "r"((r)[11]), \
           "r"((r)[12]), "r"((r)[13]), "r"((r)[14]), "r"((r)[15]), \
           "r"((r)[16]), "r"((r)[17]), "r"((r)[18]), "r"((r)[19]), \
           "r"((r)[20]), "r"((r)[21]), "r"((r)[22]), "r"((r)[23]), \
           "r"((r)[24]), "r"((r)[25]), "r"((r)[26]), "r"((r)[27]), \
           "r"((r)[28]), "r"((r)[29]), "r"((r)[30]), "r"((r)[31]) \
        : "memory")

__device__ __forceinline__ void mma_f16_ss(uint32_t d_tmem, uint64_t a_desc,
                                           uint64_t b_desc, uint32_t idesc,
                                           uint32_t enable) {
    asm volatile(
        "{ .reg .pred p; setp.ne.u32 p, %4, 0;\n\t"
        "tcgen05.mma.cta_group::1.kind::f16 [%0], %1, %2, %3, {%5,%5,%5,%5}, p;\n\t}"
        :: "r"(d_tmem), "l"(a_desc), "l"(b_desc), "r"(idesc), "r"(enable), "r"(0u)
        : "memory");
}
__device__ __forceinline__ void mma_f16_ts(uint32_t d_tmem, uint32_t a_tmem,
                                           uint64_t b_desc, uint32_t idesc,
                                           uint32_t enable) {
    asm volatile(
        "{ .reg .pred p; setp.ne.u32 p, %4, 0;\n\t"
        "tcgen05.mma.cta_group::1.kind::f16 [%0], [%1], %2, %3, {%5,%5,%5,%5}, p;\n\t}"
        :: "r"(d_tmem), "r"(a_tmem), "l"(b_desc), "r"(idesc), "r"(enable), "r"(0u)
        : "memory");
}
#endif // HAS_TCGEN05

#define SWZ(o) ((uint32_t)(o) ^ ((((uint32_t)(o)) >> 3) & 0x70u))

static __device__ __forceinline__ uint64_t make_desc(uint32_t addr) {
    const uint64_t base = (uint64_t(2) << 61) | (uint64_t(1) << 46) |
                          (uint64_t(64) << 32) | (uint64_t(1) << 16);
    return base | ((uint64_t)(addr >> 4) & 0x3FFFu);
}

// ---------------------------------------------------------------------------
// fp32 -> bf16 hi/lo split, elementwise (float4 granularity)
// ---------------------------------------------------------------------------
__global__ void __launch_bounds__(256)
cvt_hl(const float4* __restrict__ x, uint2* __restrict__ h, uint2* __restrict__ l,
       int n4)
{
    const int i = blockIdx.x * 256 + threadIdx.x;
    if (i >= n4) return;
    float4 f = x[i];
    __nv_bfloat162 h0 = __floats2bfloat162_rn(f.x, f.y);
    __nv_bfloat162 h1 = __floats2bfloat162_rn(f.z, f.w);
    float2 hf0 = __bfloat1622float2(h0), hf1 = __bfloat1622float2(h1);
    __nv_bfloat162 l0 = __floats2bfloat162_rn(f.x - hf0.x, f.y - hf0.y);
    __nv_bfloat162 l1 = __floats2bfloat162_rn(f.z - hf1.x, f.w - hf1.y);
    uint2 hv, lv;
    hv.x = bf2_bits(h0); hv.y = bf2_bits(h1);
    lv.x = bf2_bits(l0); lv.y = bf2_bits(l1);
    h[i] = hv; l[i] = lv;
}

// ---------------------------------------------------------------------------
// GEMM: out = A[4096,1024] @ B[1024,1024]^T + bias, A/B given as bf16 hi/lo.
// mode 0: fp32 row-major [m][1024]  (final output)
// mode 1: bf16 hi/lo planar [bh][s][d]   (Q, K)
// mode 2: bf16 hi/lo planar [bh][d][s]   (V transposed)
// ---------------------------------------------------------------------------
__global__ void __launch_bounds__(256, 1)
gemm_tc(const __nv_bfloat16* __restrict__ Ah, const __nv_bfloat16* __restrict__ Al,
        const __nv_bfloat16* __restrict__ Bh, const __nv_bfloat16* __restrict__ Bl,
        const float* __restrict__ bias, float* __restrict__ out32,
        __nv_bfloat16* __restrict__ outh, __nv_bfloat16* __restrict__ outl, int mode)
{
#if HAS_TCGEN05
    extern __shared__ char smc[];
    const uint32_t sb = smem_u32(smc);
    const int tid = threadIdx.x;
    const int wid = tid >> 5, lid = tid & 31;
    const int m0 = blockIdx.y * 128;
    const int n0 = blockIdx.x * 128;

    if (tid == 0) { MBAR_INIT(sb + 8, 1); MBAR_INIT(sb + 16, 1); }
    if (wid == 0) { TC_ALLOC(sb, 128); TC_RELINQ(); }
    __syncthreads();
    uint32_t tmem;
    asm("ld.shared.b32 %0, [%1];" : "=r"(tmem) : "r"(sb));

    const uint32_t idesc = (1u << 4) | (1u << 7) | (1u << 10) | (16u << 17) | (8u << 24);

    for (int ch = 0; ch < 16; ch++) {
        const int buf = ch & 1;
        const uint32_t tb = 1024u + (uint32_t)buf * 65536u;
        if (ch >= 2) MBAR_WAIT(sb + 8 + buf * 8, ((ch - 2) >> 1) & 1);
        const int k0 = ch * 64;

        // 4 tiles (Ah,Al,Bh,Bl), each 128 rows x 64 bf16 = 1024 uint4, swizzled
#pragma unroll
        for (int t = 0; t < 16; t++) {
            const int which = t >> 2;                 // 0 Ah, 1 Al, 2 Bh, 3 Bl
            const int r = (t & 3) * 256 + tid;        // 0..1023
            const int row = r >> 3, g = r & 7;
            const __nv_bfloat16* src =
                (which == 0) ? Ah : (which == 1) ? Al : (which == 2) ? Bh : Bl;
            const int base_mn = (which < 2) ? m0 : n0;
            uint4 v = *(const uint4*)&src[(size_t)(base_mn + row) * DMODEL + k0 + g * 8];
            *(uint4*)(smc + tb + (uint32_t)which * 16384u + SWZ(row * 128 + g * 16)) = v;
        }
        __syncthreads();

        if (wid == 0 && elect_one()) {
            asm volatile("fence.proxy.async.shared::cta;" ::: "memory");
            const uint64_t dAh = make_desc(sb + tb);
            const uint64_t dAl = make_desc(sb + tb + 16384);
            const uint64_t dBh = make_desc(sb + tb + 32768);
            const uint64_t dBl = make_desc(sb + tb + 49152);
#pragma unroll
            for (int ks = 0; ks < 4; ks++)
                mma_f16_ss(tmem, dAh + ks * 2, dBh + ks * 2, idesc,
                           (ch == 0 && ks == 0) ? 0u : 1u);
#pragma unroll
            for (int ks = 0; ks < 4; ks++)
                mma_f16_ss(tmem, dAh + ks * 2, dBl + ks * 2, idesc, 1u);
#pragma unroll
            for (int ks = 0; ks < 4; ks++)
                mma_f16_ss(tmem, dAl + ks * 2, dBh + ks * 2, idesc, 1u);
            TC_COMMIT(sb + 8 + buf * 8);
        }
    }

    MBAR_WAIT(sb + 16, 1);
    TC_FENCE_AFTER();

    if (wid < 4) {
        const int m = m0 + wid * 32 + lid;
        const int s = m >> 1, b = m & 1;
#pragma unroll
        for (int c0 = 0; c0 < 128; c0 += 32) {
            uint32_t r[32];
            TC_LD_X32(r, tmem + c0);
            TC_WAIT_LD();
            if (mode == 0) {
#pragma unroll
                for (int j = 0; j < 32; j += 4) {
                    float4 bv = *(const float4*)&bias[n0 + c0 + j];
                    float4 o;
                    o.x = __uint_as_float(r[j + 0]) + bv.x;
                    o.y = __uint_as_float(r[j + 1]) + bv.y;
                    o.z = __uint_as_float(r[j + 2]) + bv.z;
                    o.w = __uint_as_float(r[j + 3]) + bv.w;
                    *(float4*)&out32[(size_t)m * DMODEL + n0 + c0 + j] = o;
                }
            } else {
                const int nb = n0 + c0;
                const int h = nb >> 6, d0 = nb & 63;
                const size_t plane = (size_t)(b * NHEAD + h) * PLANE;
                __nv_bfloat16 vh[32], vl[32];
#pragma unroll
                for (int j = 0; j < 32; j++) {
                    float val = __uint_as_float(r[j]) + bias[nb + j];
                    vh[j] = __float2bfloat16_rn(val);
                    vl[j] = __float2bfloat16_rn(val - __bfloat162float(vh[j]));
                }
                if (mode == 1) {
                    const size_t base = plane + (size_t)s * 64 + d0;
#pragma unroll
                    for (int j = 0; j < 32; j += 4) {
                        __nv_bfloat162 p0, p1; uint2 u;
                        p0 = __nv_bfloat162(vh[j], vh[j + 1]);
                        p1 = __nv_bfloat162(vh[j + 2], vh[j + 3]);
                        u.x = bf2_bits(p0); u.y = bf2_bits(p1);
                        *(uint2*)&outh[base + j] = u;
                        p0 = __nv_bfloat162(vl[j], vl[j + 1]);
                        p1 = __nv_bfloat162(vl[j + 2], vl[j + 3]);
                        u.x = bf2_bits(p0); u.y = bf2_bits(p1);
                        *(uint2*)&outl[base + j] = u;
                    }
                } else {
                    const size_t base = plane + s;
#pragma unroll
                    for (int j = 0; j < 32; j++) {
                        outh[base + (size_t)(d0 + j) * S_LEN] = vh[j];
                        outl[base + (size_t)(d0 + j) * S_LEN] = vl[j];
                    }
                }
            }
        }
    }
    __syncthreads();
    if (wid == 0) TC_DEALLOC(tmem, 128);

#else  // ---------------- fp32 fallback ------------------------------------
    extern __shared__ char smc[];
    float* As = (float*)smc;
    float* Bs = As + 8 * 128;

    const int tid  = threadIdx.x;
    const int m0   = blockIdx.y * 128;
    const int n0   = blockIdx.x * 128;
    const int tx   = tid & 15;
    const int ty   = tid >> 4;
    const int lrow = tid >> 1;
    const int lc   = (tid & 1) * 4;

    float acc[8][8];
#pragma unroll
    for (int i = 0; i < 8; i++)
#pragma unroll
        for (int j = 0; j < 8; j++) acc[i][j] = 0.0f;

    for (int k0 = 0; k0 < DMODEL; k0 += 8) {
        float av[4], bv[4];
#pragma unroll
        for (int j = 0; j < 4; j++) {
            size_t ai = (size_t)(m0 + lrow) * DMODEL + k0 + lc + j;
            size_t bi = (size_t)(n0 + lrow) * DMODEL + k0 + lc + j;
            av[j] = __bfloat162float(Ah[ai]) + __bfloat162float(Al[ai]);
            bv[j] = __bfloat162float(Bh[bi]) + __bfloat162float(Bl[bi]);
        }
        __syncthreads();
#pragma unroll
        for (int j = 0; j < 4; j++) {
            As[(lc + j) * 128 + lrow] = av[j];
            Bs[(lc + j) * 128 + lrow] = bv[j];
        }
        __syncthreads();
#pragma unroll
        for (int kk = 0; kk < 8; kk++) {
            float a[8], b[8];
            *(float4*)&a[0] = *(const float4*)&As[kk * 128 + ty * 8];
            *(float4*)&a[4] = *(const float4*)&As[kk * 128 + ty * 8 + 4];
            *(float4*)&b[0] = *(const float4*)&Bs[kk * 128 + tx * 8];
            *(float4*)&b[4] = *(const float4*)&Bs[kk * 128 + tx * 8 + 4];
#pragma unroll
            for (int i = 0; i < 8; i++)
#pragma unroll
                for (int j = 0; j < 8; j++)
                    acc[i][j] = fmaf(a[i], b[j], acc[i][j]);
        }
    }

#pragma unroll
    for (int i = 0; i < 8; i++) {
        const int m = m0 + ty * 8 + i;
        const int s = m >> 1, b = m & 1;
#pragma unroll
        for (int j = 0; j < 8; j++) {
            const int n = n0 + tx * 8 + j;
            const float val = acc[i][j] + bias[n];
            if (mode == 0) {
                out32[(size_t)m * DMODEL + n] = val;
            } else {
                const int h = n >> 6, d = n & 63;
                const size_t plane = (size_t)(b * NHEAD + h) * PLANE;
                const size_t idx = (mode == 1) ? plane + (size_t)s * 64 + d
                                               : plane + (size_t)d * S_LEN + s;
                __nv_bfloat16 hv = __float2bfloat16_rn(val);
                outh[idx] = hv;
                outl[idx] = __float2bfloat16_rn(val - __bfloat162float(hv));
            }
        }
    }
#endif
}

// ---------------------------------------------------------------------------
// tcgen05 flash attention, software-pipelined.
// Grid (16, 32), 128 threads. TMEM: S0@0, S1@64, delta@128, Ph@192, Pl@224.
// smem: ctrl | QH@1024 QL@17408 | buf0@33792 (KH,KL,VH,VL 8K each) | buf1@66560
// ---------------------------------------------------------------------------
#define FQH  1024u
#define FQL  17408u
#define FBUF 33792u
#define FSMEM 99328

__global__ void __launch_bounds__(128, 1)
flash_tc()
{
#if HAS_TCGEN05
    extern __shared__ char smc[];
    const uint32_t sb = smem_u32(smc);
    const int tid  = threadIdx.x;
    const int wid  = tid >> 5;
    const int lane = tid & 31;
    const int bh   = blockIdx.y;
    const int q0   = blockIdx.x * 128;
    const int bb   = bh >> 4;
    const int hh   = bh & 15;
    const size_t plane = (size_t)bh * PLANE;

    if (tid == 0) { MBAR_INIT(sb + 8, 1); MBAR_INIT(sb + 16, 1); }
    if (wid == 0) { TC_ALLOC(sb, 256); TC_RELINQ(); }
    __syncthreads();
    uint32_t tmem;
    asm("ld.shared.b32 %0, [%1];" : "=r"(tmem) : "r"(sb));

    const uint32_t idesc = (1u << 4) | (1u << 7) | (1u << 10) | (8u << 17) | (8u << 24);
    const uint32_t warp_off = (uint32_t)wid << 21;

    // ---- Q tile (128 x 64) hi/lo, straight uint4 copy into swizzled smem ----
#pragma unroll
    for (int t = 0; t < 8; t++) {
        const int idx = t * 128 + tid;          // 1024 uint4 per half
        const int row = idx >> 3, g = idx & 7;
        const size_t off = plane + (size_t)(q0 + row) * 64 + g * 8;
        *(uint4*)(smc + FQH + SWZ(row * 128 + g * 16)) = *(const uint4*)&g_Qh[off];
        *(uint4*)(smc + FQL + SWZ(row * 128 + g * 16)) = *(const uint4*)&g_Ql[off];
    }
    // ---- KV tile 0 into buf0 ----
#pragma unroll
    for (int t = 0; t < 4; t++) {
        const int idx = t * 128 + tid;          // 512 uint4 per half
        const int row = idx >> 3, g = idx & 7;
        const size_t koff = plane + (size_t)row * 64 + g * 8;          // K rows = kk
        *(uint4*)(smc + FBUF + SWZ(row * 128 + g * 16))         = *(const uint4*)&g_Kh[koff];
        *(uint4*)(smc + FBUF + 8192 + SWZ(row * 128 + g * 16))  = *(const uint4*)&g_Kl[koff];
        const size_t voff = plane + (size_t)row * S_LEN + g * 8;       // V rows = d
        *(uint4*)(smc + FBUF + 16384 + SWZ(row * 128 + g * 16)) = *(const uint4*)&g_Vth[voff];
        *(uint4*)(smc + FBUF + 24576 + SWZ(row * 128 + g * 16)) = *(const uint4*)&g_Vtl[voff];
    }
    __syncthreads();

    const uint64_t dQh = make_desc(sb + FQH);
    const uint64_t dQl = make_desc(sb + FQL);

    if (wid == 0 && elect_one()) {
        asm volatile("fence.proxy.async.shared::cta;" ::: "memory");
        const uint64_t dKh = make_desc(sb + FBUF);
        const uint64_t dKl = make_desc(sb + FBUF + 8192);
#pragma unroll
        for (int ks = 0; ks < 4; ks++)
            mma_f16_ss(tmem, dQh + ks * 2, dKh + ks * 2, idesc, ks == 0 ? 0u : 1u);
#pragma unroll
        for (int ks = 0; ks < 4; ks++)
            mma_f16_ss(tmem, dQh + ks * 2, dKl + ks * 2, idesc, 1u);
#pragma unroll
        for (int ks = 0; ks < 4; ks++)
            mma_f16_ss(tmem, dQl + ks * 2, dKh + ks * 2, idesc, 1u);
        TC_COMMIT(sb + 8);
    }

    float o[64];
#pragma unroll
    for (int j = 0; j < 64; j++) o[j] = 0.0f;
    float mrun = -1e30f, lrun = 0.0f, a_prev = 0.0f, rs_prev = 0.0f;

    for (int kt = 0; kt < 32; kt++) {
        const int cur = kt & 1;
        const uint32_t bufc = FBUF + (uint32_t)cur * 32768u;
        const uint32_t bufn = FBUF + (uint32_t)(cur ^ 1) * 32768u;
        const uint32_t sS = tmem + (uint32_t)cur * 64u;

        // --- prefetch K(kt+1) into buf nxt (its last reader S(kt-1) is done) ---
        if (kt < 31) {
            const int k0n = (kt + 1) * 64;
#pragma unroll
            for (int t = 0; t < 4; t++) {
                const int idx = t * 128 + tid;
                const int row = idx >> 3, g = idx & 7;
                const size_t koff = plane + (size_t)(k0n + row) * 64 + g * 8;
                *(uint4*)(smc + bufn + SWZ(row * 128 + g * 16))        = *(const uint4*)&g_Kh[koff];
                *(uint4*)(smc + bufn + 8192 + SWZ(row * 128 + g * 16)) = *(const uint4*)&g_Kl[koff];
            }
        }

        // --- wait S(kt), load scores (row = this thread's q) ---
        MBAR_WAIT(sb + 8, kt & 1);
        TC_FENCE_AFTER();
        float p[64];
        {
            uint32_t r[32];
            TC_LD_X32(r, sS);
            TC_WAIT_LD();
#pragma unroll
            for (int j = 0; j < 32; j++) p[j] = __uint_as_float(r[j]) * 0.125f;
            TC_LD_X32(r, sS + 32);
            TC_WAIT_LD();
#pragma unroll
            for (int j = 0; j < 32; j++) p[32 + j] = __uint_as_float(r[j]) * 0.125f;
        }

        // --- softmax ---
        float mx = p[0];
#pragma unroll
        for (int j = 1; j < 64; j++) mx = fmaxf(mx, p[j]);
        const float mnew  = fmaxf(mrun, mx);
        const float a_cur = __expf(mrun - mnew);
        float rs = 0.0f;
#pragma unroll
        for (int j = 0; j < 64; j++) {
            p[j] = __expf(p[j] - mnew);
            rs += p[j];
        }
        mrun = mnew;

        // --- fold delta(kt-1) with previous alpha ---
        if (kt > 0) {
            MBAR_WAIT(sb + 16, (kt - 1) & 1);
            TC_FENCE_AFTER();
            uint32_t r[32];
            TC_LD_X32(r, tmem + 128);
            TC_WAIT_LD();
#pragma unroll
            for (int j = 0; j < 32; j++) o[j] = a_prev * o[j] + __uint_as_float(r[j]);
            TC_LD_X32(r, tmem + 160);
            TC_WAIT_LD();
#pragma unroll
            for (int j = 0; j < 32; j++) o[32 + j] = a_prev * o[32 + j] + __uint_as_float(r[j]);
            lrun = a_prev * lrun + rs_prev;
        }
        a_prev = a_cur; rs_prev = rs;

        // --- V(kt+1) store (V buf nxt free: PV(kt-1) done) ---
        if (kt < 31) {
            const int k0n = (kt + 1) * 64;
#pragma unroll
            for (int t = 0; t < 4; t++) {
                const int idx = t * 128 + tid;
                const int row = idx >> 3, g = idx & 7;
                const size_t voff = plane + (size_t)row * S_LEN + k0n + g * 8;
                *(uint4*)(smc + bufn + 16384 + SWZ(row * 128 + g * 16)) = *(const uint4*)&g_Vth[voff];
                *(uint4*)(smc + bufn + 24576 + SWZ(row * 128 + g * 16)) = *(const uint4*)&g_Vtl[voff];
            }
        }

        // --- P -> bf16 hi/lo, STTM (region free: PV(kt-1) done) ---
        {
            uint32_t ph[32], pl[32];
#pragma unroll
            for (int j = 0; j < 32; j++) {
                __nv_bfloat162 h = __floats2bfloat162_rn(p[2 * j], p[2 * j + 1]);
                float2 hf = __bfloat1622float2(h);
                __nv_bfloat162 l = __floats2bfloat162_rn(p[2 * j] - hf.x, p[2 * j + 1] - hf.y);
                ph[j] = bf2_bits(h);
                pl[j] = bf2_bits(l);
            }
            TC_ST_X32(tmem + 192 + warp_off, ph);
            TC_ST_X32(tmem + 224 + warp_off, pl);
            TC_WAIT_ST();
        }
        TC_FENCE_BEFORE();
        __syncthreads();

        // --- enqueue PV(kt) then S(kt+1) on the in-order tensor pipe ---
        if (wid == 0 && elect_one()) {
            TC_FENCE_AFTER();
            asm volatile("fence.proxy.async.shared::cta;" ::: "memory");
            const uint64_t dVh = make_desc(sb + bufc + 16384);
            const uint64_t dVl = make_desc(sb + bufc + 24576);
#pragma unroll
            for (int ks = 0; ks < 4; ks++)
                mma_f16_ts(tmem + 128, tmem + 192 + ks * 8, dVh + ks * 2, idesc,
                           ks == 0 ? 0u : 1u);
#pragma unroll
            for (int ks = 0; ks < 4; ks++)
                mma_f16_ts(tmem + 128, tmem + 192 + ks * 8, dVl + ks * 2, idesc, 1u);
#pragma unroll
            for (int ks = 0; ks < 4; ks++)
                mma_f16_ts(tmem + 128, tmem + 224 + ks * 8, dVh + ks * 2, idesc, 1u);
            TC_COMMIT(sb + 16);
            if (kt < 31) {
                const uint64_t dKh = make_desc(sb + bufn);
                const uint64_t dKl = make_desc(sb + bufn + 8192);
                const uint32_t sN = tmem + (uint32_t)(cur ^ 1) * 64u;
#pragma unroll
                for (int ks = 0; ks < 4; ks++)
                    mma_f16_ss(sN, dQh + ks * 2, dKh + ks * 2, idesc, ks == 0 ? 0u : 1u);
#pragma unroll
                for (int ks = 0; ks < 4; ks++)
                    mma_f16_ss(sN, dQh + ks * 2, dKl + ks * 2, idesc, 1u);
#pragma unroll
                for (int ks = 0; ks < 4; ks++)
                    mma_f16_ss(sN, dQl + ks * 2, dKh + ks * 2, idesc, 1u);
                TC_COMMIT(sb + 8);
            }
        }
    }

    // --- epilogue: fold delta(31), normalize, write bf16 hi/lo ---
    MBAR_WAIT(sb + 16, 1);
    TC_FENCE_AFTER();
    {
        uint32_t r[32];
        TC_LD_X32(r, tmem + 128);
        TC_WAIT_LD();
#pragma unroll
        for (int j = 0; j < 32; j++) o[j] = a_prev * o[j] + __uint_as_float(r[j]);
        TC_LD_X32(r, tmem + 160);
        TC_WAIT_LD();
#pragma unroll
        for (int j = 0; j < 32; j++) o[32 + j] = a_prev * o[32 + j] + __uint_as_float(r[j]);
        lrun = a_prev * lrun + rs_prev;
    }
    TC_FENCE_BEFORE();

    const float inv = 1.0f / lrun;
    const int qg = q0 + wid * 32 + lane;
    const size_t orow = ((size_t)qg * NB + bb) * DMODEL + (size_t)hh * DKH;
#pragma unroll
    for (int j = 0; j < 64; j += 4) {
        float v0 = o[j] * inv, v1 = o[j + 1] * inv, v2 = o[j + 2] * inv, v3 = o[j + 3] * inv;
        __nv_bfloat16 h0 = __float2bfloat16_rn(v0), h1 = __float2bfloat16_rn(v1);
        __nv_bfloat16 h2 = __float2bfloat16_rn(v2), h3 = __float2bfloat16_rn(v3);
        uint2 uh, ul;
        uh.x = bf2_bits(__nv_bfloat162(h0, h1));
        uh.y = bf2_bits(__nv_bfloat162(h2, h3));
        ul.x = bf2_bits(__nv_bfloat162(
                   __float2bfloat16_rn(v0 - __bfloat162float(h0)),
                   __float2bfloat16_rn(v1 - __bfloat162float(h1))));
        ul.y = bf2_bits(__nv_bfloat162(
                   __float2bfloat16_rn(v2 - __bfloat162float(h2)),
                   __float2bfloat16_rn(v3 - __bfloat162float(h3))));
        *(uint2*)&g_AOh[orow + j] = uh;
        *(uint2*)&g_AOl[orow + j] = ul;
    }
    __syncthreads();
    if (wid == 0) TC_DEALLOC(tmem, 256);

#else  // ---------------- scalar fallback ----------------------------------
    const int tid = threadIdx.x;
    const int bh  = blockIdx.y;
    const int q0  = blockIdx.x * 128;
    const int bb  = bh >> 4;
    const int hh  = bh & 15;
    const size_t plane = (size_t)bh * PLANE;

    const int qg = q0 + tid;
    float qr[64];
#pragma unroll
    for (int d = 0; d < 64; d++) {
        size_t i = plane + (size_t)qg * 64 + d;
        qr[d] = (__bfloat162float(g_Qh[i]) + __bfloat162float(g_Ql[i])) * 0.125f;
    }

    float o[64];
#pragma unroll
    for (int d = 0; d < 64; d++) o[d] = 0.0f;
    float m = -1e30f, l = 0.0f;

    for (int kk = 0; kk < S_LEN; kk++) {
        float s = 0.0f;
        for (int d = 0; d < 64; d++) {
            size_t i = plane + (size_t)kk * 64 + d;
            s = fmaf(qr[d], __bfloat162float(g_Kh[i]) + __bfloat162float(g_Kl[i]), s);
        }
        const float mn = fmaxf(m, s);
        const float al = __expf(m - mn);
        const float pr = __expf(s - mn);
        m = mn; l = l * al + pr;
        for (int d = 0; d < 64; d++) {
            size_t i = plane + (size_t)d * S_LEN + kk;
            o[d] = o[d] * al + pr * (__bfloat162float(g_Vth[i]) + __bfloat162float(g_Vtl[i]));
        }
    }
    const float inv = 1.0f / l;
    const size_t orow = ((size_t)qg * NB + bb) * DMODEL + (size_t)hh * DKH;
    for (int d = 0; d < 64; d++) {
        float v = o[d] * inv;
        __nv_bfloat16 hv = __float2bfloat16_rn(v);
        g_AOh[orow + d] = hv;
        g_AOl[orow + d] = __float2bfloat16_rn(v - __bfloat162float(hv));
    }
#endif
}

// ---------------------------------------------------------------------------
extern "C" void kernel_launch(void* const* d_in, const int* in_sizes, int n_in,
                              void* d_out, int out_size)
{
    const float* q  = (const float*)d_in[0];
    const float* k  = (const float*)d_in[1];
    const float* v  = (const float*)d_in[2];
    const float* Wq = (const float*)d_in[3];
    const float* bq = (const float*)d_in[4];
    const float* Wk = (const float*)d_in[5];
    const float* bk = (const float*)d_in[6];
    const float* Wv = (const float*)d_in[7];
    const float* bv = (const float*)d_in[8];
    const float* Wo = (const float*)d_in[9];
    const float* bo = (const float*)d_in[10];
    float* out = (float*)d_out;

    __nv_bfloat16 *qh, *ql, *kh, *kl, *vh, *vl;
    __nv_bfloat16 *wqh, *wql, *wkh, *wkl, *wvh, *wvl, *woh, *wol;
    __nv_bfloat16 *Qh, *Ql, *Kh, *Kl, *Vth, *Vtl, *AOh, *AOl;
    cudaGetSymbolAddress((void**)&qh, g_qh);   cudaGetSymbolAddress((void**)&ql, g_ql);
    cudaGetSymbolAddress((void**)&kh, g_kh);   cudaGetSymbolAddress((void**)&kl, g_kl);
    cudaGetSymbolAddress((void**)&vh, g_vh);   cudaGetSymbolAddress((void**)&vl, g_vl);
    cudaGetSymbolAddress((void**)&wqh, g_wqh); cudaGetSymbolAddress((void**)&wql, g_wql);
    cudaGetSymbolAddress((void**)&wkh, g_wkh); cudaGetSymbolAddress((void**)&wkl, g_wkl);
    cudaGetSymbolAddress((void**)&wvh, g_wvh); cudaGetSymbolAddress((void**)&wvl, g_wvl);
    cudaGetSymbolAddress((void**)&woh, g_woh); cudaGetSymbolAddress((void**)&wol, g_wol);
    cudaGetSymbolAddress((void**)&Qh, g_Qh);   cudaGetSymbolAddress((void**)&Ql, g_Ql);
    cudaGetSymbolAddress((void**)&Kh, g_Kh);   cudaGetSymbolAddress((void**)&Kl, g_Kl);
    cudaGetSymbolAddress((void**)&Vth, g_Vth); cudaGetSymbolAddress((void**)&Vtl, g_Vtl);
    cudaGetSymbolAddress((void**)&AOh, g_AOh); cudaGetSymbolAddress((void**)&AOl, g_AOl);

    const int gsmem = 1024 + 2 * 65536;
    cudaFuncSetAttribute(gemm_tc, cudaFuncAttributeMaxDynamicSharedMemorySize, gsmem);
    cudaFuncSetAttribute(flash_tc, cudaFuncAttributeMaxDynamicSharedMemorySize, FSMEM);

    // ---- converts ----
    const int nX4 = MROWS * DMODEL / 4;   // 1,048,576
    const int nW4 = DMODEL * DMODEL / 4;  // 262,144
    cvt_hl<<<nX4 / 256, 256>>>((const float4*)q, (uint2*)qh, (uint2*)ql, nX4);
    cvt_hl<<<nX4 / 256, 256>>>((const float4*)k, (uint2*)kh, (uint2*)kl, nX4);
    cvt_hl<<<nX4 / 256, 256>>>((const float4*)v, (uint2*)vh, (uint2*)vl, nX4);
    cvt_hl<<<nW4 / 256, 256>>>((const float4*)Wq, (uint2*)wqh, (uint2*)wql, nW4);
    cvt_hl<<<nW4 / 256, 256>>>((const float4*)Wk, (uint2*)wkh, (uint2*)wkl, nW4);
    cvt_hl<<<nW4 / 256, 256>>>((const float4*)Wv, (uint2*)wvh, (uint2*)wvl, nW4);
    cvt_hl<<<nW4 / 256, 256>>>((const float4*)Wo, (uint2*)woh, (uint2*)wol, nW4);

    const dim3 ggrid(DMODEL / 128, MROWS / 128);   // (8, 32)

    gemm_tc<<<ggrid, 256, gsmem>>>(qh, ql, wqh, wql, bq, nullptr, Qh, Ql, 1);
    gemm_tc<<<ggrid, 256, gsmem>>>(kh, kl, wkh, wkl, bk, nullptr, Kh, Kl, 1);
    gemm_tc<<<ggrid, 256, gsmem>>>(vh, vl, wvh, wvl, bv, nullptr, Vth, Vtl, 2);

    flash_tc<<<dim3(S_LEN / 128, NB * NHEAD), 128, FSMEM>>>();

    gemm_tc<<<ggrid, 256, gsmem>>>(AOh, AOl, woh, wol, bo, out, nullptr, nullptr, 0);
}